// round 6
// baseline (speedup 1.0000x reference)
#include <cuda_runtime.h>
#include <cstdint>

typedef unsigned long long ull;

#define IMG_W 512
#define ROWB  2048    // bytes per image row
#define OUT_W 507
#define NSTR  3       // strips per image
#define STRIP 169     // output rows per strip (3*169 = 507 exact)
#define NROWS 174     // input rows per strip (STRIP + 5), divisible by 6
#define NB_MM 1184

// ---------------- device-global scratch (no allocs) --------------------------
__device__ float    g_mn[NB_MM], g_mx[NB_MM];
__device__ float    g_part[512];
__device__ unsigned g_done;          // zero-init; last block resets each run

// ---------------- packed f32x2 helpers (sm_103a) ------------------------------
static __device__ __forceinline__ ull pk2(float a, float b){
    ull r; asm("mov.b64 %0, {%1, %2};" : "=l"(r) : "f"(a), "f"(b)); return r;
}
static __device__ __forceinline__ ull mul2(ull a, ull b){
    ull r; asm("mul.rn.f32x2 %0, %1, %2;" : "=l"(r) : "l"(a), "l"(b)); return r;
}
static __device__ __forceinline__ ull add2(ull a, ull b){
    ull r; asm("add.rn.f32x2 %0, %1, %2;" : "=l"(r) : "l"(a), "l"(b)); return r;
}
static __device__ __forceinline__ ull fma2(ull a, ull b, ull c){
    ull r; asm("fma.rn.f32x2 %0, %1, %2, %3;" : "=l"(r) : "l"(a), "l"(b), "l"(c)); return r;
}
static __device__ __forceinline__ float lo2(ull a){ return __uint_as_float((unsigned)a); }
static __device__ __forceinline__ float hi2(ull a){ return __uint_as_float((unsigned)(a >> 32)); }
static __device__ __forceinline__ void pref2(const void* p){
    asm volatile("prefetch.global.L2 [%0];" :: "l"(p));
}

// ---------------- gaussian weights (w_size=6, sigma=1.5, normalized) ---------
#define GW0 0.03802585f
#define GW1 0.11551231f
#define GW2 0.22498725f
#define GW3 0.28097506f

// ---------------- min/max partials kernel -------------------------------------
__global__ void k_minmax(const float4* __restrict__ x, int n4){
    float mn = 3.4028235e38f, mx = -3.4028235e38f;
    int stride = gridDim.x * blockDim.x;
    for (int i = blockIdx.x * blockDim.x + threadIdx.x; i < n4; i += stride){
        float4 v = x[i];
        mn = fminf(mn, fminf(fminf(v.x, v.y), fminf(v.z, v.w)));
        mx = fmaxf(mx, fmaxf(fmaxf(v.x, v.y), fmaxf(v.z, v.w)));
    }
    #pragma unroll
    for (int o = 16; o > 0; o >>= 1){
        mn = fminf(mn, __shfl_xor_sync(0xFFFFFFFFu, mn, o));
        mx = fmaxf(mx, __shfl_xor_sync(0xFFFFFFFFu, mx, o));
    }
    __shared__ float smn[8], smx[8];
    int wid = threadIdx.x >> 5, lane = threadIdx.x & 31;
    if (lane == 0){ smn[wid] = mn; smx[wid] = mx; }
    __syncthreads();
    if (threadIdx.x == 0){
        mn = smn[0]; mx = smx[0];
        #pragma unroll
        for (int w = 1; w < 8; ++w){ mn = fminf(mn, smn[w]); mx = fmaxf(mx, smx[w]); }
        g_mn[blockIdx.x] = mn;
        g_mx[blockIdx.x] = mx;
    }
}

// 6-tap packed MAC: taps [GW0,GW1,GW2,GW3,GW2,GW1]
#define HMAC(d, v0, v1, v2, v3, v4, v5) \
    d = mul2((v0), W0); d = fma2((v1), W1, d); d = fma2((v2), W2, d); \
    d = fma2((v3), W3, d); d = fma2((v4), W2, d); d = fma2((v5), W1, d)

// load one input row (both tensors) into ull set S. OFF = compile-time byte offset
// from the group base pointers xr/yr (which track row i6+2).
#define LOADROW(S, OFF) do { \
    rx[S][0] = *(const ull*)(xr + (OFF)); \
    rx[S][1] = *(const ull*)(xr + (OFF) + d1); \
    rx[S][2] = *(const ull*)(xr + (OFF) + d2); \
    rx[S][3] = *(const ull*)(xr + (OFF) + d3); \
    ry[S][0] = *(const ull*)(yr + (OFF)); \
    ry[S][1] = *(const ull*)(yr + (OFF) + d1); \
    ry[S][2] = *(const ull*)(yr + (OFF) + d2); \
    ry[S][3] = *(const ull*)(yr + (OFF) + d3); \
} while(0)

// One row-step. P literal 0..5. DOOUT/DOLOAD/DOPREF compile-time 0/1.
// Consumes set P%3; LDGs 2 rows ahead into set (P+2)%3; L2-prefetches 6 ahead.
#define ROW_STEP(P, DOOUT, DOLOAD, DOPREF) do { \
    if (DOPREF){ pref2(xp + (P)*ROWB); pref2(yp + (P)*ROWB); } \
    if (DOLOAD){ LOADROW(((P)+2)%3, (P)*ROWB); } \
    { \
        ull xp0_ = rx[(P)%3][0], xp1_ = rx[(P)%3][1], xp2_ = rx[(P)%3][2], xp3_ = rx[(P)%3][3]; \
        ull yp0_ = ry[(P)%3][0], yp1_ = ry[(P)%3][1], yp2_ = ry[(P)%3][2], yp3_ = ry[(P)%3][3]; \
        ull pp0_ = fma2(yp0_, yp0_, mul2(xp0_, xp0_)); \
        ull pp1_ = fma2(yp1_, yp1_, mul2(xp1_, xp1_)); \
        ull pp2_ = fma2(yp2_, yp2_, mul2(xp2_, xp2_)); \
        ull pp3_ = fma2(yp3_, yp3_, mul2(xp3_, xp3_)); \
        ull qq0_ = mul2(xp0_, yp0_), qq1_ = mul2(xp1_, yp1_); \
        ull qq2_ = mul2(xp2_, yp2_), qq3_ = mul2(xp3_, yp3_); \
        { ull d_; HMAC(d_, xp0_, pk2(hi2(xp0_), lo2(xp1_)), xp1_, pk2(hi2(xp1_), lo2(xp2_)), xp2_, pk2(hi2(xp2_), lo2(xp3_))); ring[(P)][0] = d_; } \
        { ull d_; HMAC(d_, yp0_, pk2(hi2(yp0_), lo2(yp1_)), yp1_, pk2(hi2(yp1_), lo2(yp2_)), yp2_, pk2(hi2(yp2_), lo2(yp3_))); ring[(P)][1] = d_; } \
        { ull d_; HMAC(d_, pp0_, pk2(hi2(pp0_), lo2(pp1_)), pp1_, pk2(hi2(pp1_), lo2(pp2_)), pp2_, pk2(hi2(pp2_), lo2(pp3_))); ring[(P)][2] = d_; } \
        { ull d_; HMAC(d_, qq0_, pk2(hi2(qq0_), lo2(qq1_)), qq1_, pk2(hi2(qq1_), lo2(qq2_)), qq2_, pk2(hi2(qq2_), lo2(qq3_))); ring[(P)][3] = d_; } \
    } \
    if (DOOUT){ \
        ull v0_, v1_, v2_, v3_; \
        HMAC(v0_, ring[((P)+1)%6][0], ring[((P)+2)%6][0], ring[((P)+3)%6][0], ring[((P)+4)%6][0], ring[((P)+5)%6][0], ring[(P)][0]); \
        HMAC(v1_, ring[((P)+1)%6][1], ring[((P)+2)%6][1], ring[((P)+3)%6][1], ring[((P)+4)%6][1], ring[((P)+5)%6][1], ring[(P)][1]); \
        HMAC(v2_, ring[((P)+1)%6][2], ring[((P)+2)%6][2], ring[((P)+3)%6][2], ring[((P)+4)%6][2], ring[((P)+5)%6][2], ring[(P)][2]); \
        HMAC(v3_, ring[((P)+1)%6][3], ring[((P)+2)%6][3], ring[((P)+3)%6][3], ring[((P)+4)%6][3], ring[((P)+5)%6][3], ring[(P)][3]); \
        ull mu12_ = mul2(v0_, v1_); \
        ull msum_ = fma2(v1_, v1_, mul2(v0_, v0_)); \
        ull t1_ = fma2(mu12_, NTWO, fma2(v3_, TWO, C2p)); \
        ull t2_ = fma2(msum_, NONE, add2(v2_, C2p)); \
        ull num_ = mul2(fma2(mu12_, TWO, C1p), t1_); \
        ull den_ = mul2(add2(msum_, C1p), t2_); \
        float nl_ = lo2(num_), nh_ = hi2(num_); \
        float dl_ = lo2(den_), dh_ = hi2(den_); \
        if (hi_ok)      acc += __fdividef(fmaf(nl_, dh_, nh_ * dl_), dl_ * dh_); \
        else if (lo_ok) acc += __fdividef(nl_, dl_); \
    } \
} while(0)

__global__ void __launch_bounds__(256, 2)
k_ssim(const float* __restrict__ X, const float* __restrict__ Y,
       float* __restrict__ out, int nblk, double inv_n){
    __shared__ float    smn[8], smx[8], sC[2];
    __shared__ double   sd[8];
    __shared__ unsigned s_tick;

    const int tid   = threadIdx.x;
    const int c0    = tid * 2;
    const int bx    = blockIdx.x;
    const int strip = bx % NSTR;
    const int img   = bx / NSTR;
    const int base  = strip * STRIP;
    const float* xi = X + (size_t)img * (IMG_W * IMG_W);
    const float* yi = Y + (size_t)img * (IMG_W * IMG_W);
    const bool lo_ok = (c0     < OUT_W);
    const bool hi_ok = (c0 + 1 < OUT_W);

    // clamped column byte deltas (edge threads read in-bounds garbage; masked)
    const int o0 = c0;
    const int d1 = (min(c0 + 2, 510) - c0) * 4;
    const int d2 = (min(c0 + 4, 510) - c0) * 4;
    const int d3 = (min(c0 + 6, 510) - c0) * 4;

    // group base pointers: xr/yr -> LDG row (group_i+2); xp/yp -> prefetch row (group_i+6)
    const char* xr = (const char*)(xi + (size_t)(base + 2) * IMG_W + o0);
    const char* yr = (const char*)(yi + (size_t)(base + 2) * IMG_W + o0);
    const char* xp = (const char*)(xi + (size_t)(base + 6) * IMG_W + o0);
    const char* yp = (const char*)(yi + (size_t)(base + 6) * IMG_W + o0);

    // ---- reduce min/max partials -> C1, C2 ----
    {
        float mn = 3.4028235e38f, mx = -3.4028235e38f;
        for (int i = tid; i < NB_MM; i += 256){
            mn = fminf(mn, g_mn[i]);
            mx = fmaxf(mx, g_mx[i]);
        }
        #pragma unroll
        for (int o = 16; o > 0; o >>= 1){
            mn = fminf(mn, __shfl_xor_sync(0xFFFFFFFFu, mn, o));
            mx = fmaxf(mx, __shfl_xor_sync(0xFFFFFFFFu, mx, o));
        }
        int wid = tid >> 5, lane = tid & 31;
        if (lane == 0){ smn[wid] = mn; smx[wid] = mx; }
    }

    // register pipeline: 3 rotating row sets (u64 packed pairs)
    ull rx[3][4], ry[3][4];
    LOADROW(0, -2*ROWB);           // row base
    LOADROW(1, -1*ROWB);           // row base+1
    #pragma unroll
    for (int r = -4; r < 0; ++r){  // L2-prefetch rows base+2..base+5
        pref2(xp + r*ROWB);
        pref2(yp + r*ROWB);
    }

    __syncthreads();
    if (tid == 0){
        float mn = smn[0], mx = smx[0];
        #pragma unroll
        for (int w = 1; w < 8; ++w){ mn = fminf(mn, smn[w]); mx = fmaxf(mx, smx[w]); }
        float Ldyn = (mx > 128.0f ? 255.0f : 1.0f) - (mn < -0.5f ? -1.0f : 0.0f);
        sC[0] = (0.01f * Ldyn) * (0.01f * Ldyn);
        sC[1] = (0.03f * Ldyn) * (0.03f * Ldyn);
    }
    __syncthreads();

    const float C1 = sC[0], C2 = sC[1];
    const ull W0  = pk2(GW0, GW0), W1 = pk2(GW1, GW1);
    const ull W2  = pk2(GW2, GW2), W3 = pk2(GW3, GW3);
    const ull C1p = pk2(C1, C1),   C2p = pk2(C2, C2);
    const ull TWO = pk2(2.0f, 2.0f), NTWO = pk2(-2.0f, -2.0f), NONE = pk2(-1.0f, -1.0f);

    ull ring[6][4];
    float acc = 0.0f;

    // ---- group 0 (rows 0..5): warm-up, first output at row 5 ----
    ROW_STEP(0, 0, 1, 1);
    ROW_STEP(1, 0, 1, 1);
    ROW_STEP(2, 0, 1, 1);
    ROW_STEP(3, 0, 1, 1);
    ROW_STEP(4, 0, 1, 1);
    ROW_STEP(5, 1, 1, 1);
    xr += 6*ROWB; yr += 6*ROWB; xp += 6*ROWB; yp += 6*ROWB;

    // ---- middle groups (rows 6..167): fully clean, no predicates ----
    #pragma unroll 1
    for (int g = 0; g < 27; ++g){
        ROW_STEP(0, 1, 1, 1);
        ROW_STEP(1, 1, 1, 1);
        ROW_STEP(2, 1, 1, 1);
        ROW_STEP(3, 1, 1, 1);
        ROW_STEP(4, 1, 1, 1);
        ROW_STEP(5, 1, 1, 1);
        xr += 6*ROWB; yr += 6*ROWB; xp += 6*ROWB; yp += 6*ROWB;
    }

    // ---- tail group (rows 168..173): loads stop at row 173, no prefetch ----
    ROW_STEP(0, 1, 1, 0);   // loads row 170
    ROW_STEP(1, 1, 1, 0);   // loads row 171
    ROW_STEP(2, 1, 1, 0);   // loads row 172
    ROW_STEP(3, 1, 1, 0);   // loads row 173 (last input row)
    ROW_STEP(4, 1, 0, 0);
    ROW_STEP(5, 1, 0, 0);

    // ---- block reduction -> partial; last block finishes ----
    #pragma unroll
    for (int o = 16; o > 0; o >>= 1)
        acc += __shfl_xor_sync(0xFFFFFFFFu, acc, o);
    const int wid = tid >> 5, lane = tid & 31;
    if (lane == 0) smn[wid] = acc;
    __syncthreads();
    if (tid == 0){
        float s = smn[0];
        #pragma unroll
        for (int w = 1; w < 8; ++w) s += smn[w];
        g_part[bx] = s;
        __threadfence();
        s_tick = atomicAdd(&g_done, 1u);
    }
    __syncthreads();

    if (s_tick == (unsigned)(nblk - 1)){
        double s = 0.0;
        for (int i = tid; i < nblk; i += 256) s += (double)g_part[i];
        #pragma unroll
        for (int o = 16; o > 0; o >>= 1)
            s += __shfl_xor_sync(0xFFFFFFFFu, s, o);
        if (lane == 0) sd[wid] = s;
        __syncthreads();
        if (tid == 0){
            double t = 0.0;
            #pragma unroll
            for (int w = 0; w < 8; ++w) t += sd[w];
            out[0] = (float)((1.0 - t * inv_n) * 0.5);
            g_done = 0u;   // reset for next graph replay
        }
    }
}

// ---------------- launch --------------------------------------------------------
extern "C" void kernel_launch(void* const* d_in, const int* in_sizes, int n_in,
                              void* d_out, int out_size){
    const float* X = (const float*)d_in[0];  // y_pred
    const float* Y = (const float*)d_in[1];  // y_true

    const int nelem = in_sizes[0];
    const int nimg  = nelem / (IMG_W * IMG_W);
    const int nblk  = NSTR * nimg;
    const double n_out = (double)nimg * (double)OUT_W * (double)OUT_W;

    k_minmax<<<NB_MM, 256>>>((const float4*)X, nelem / 4);
    k_ssim<<<nblk, 256>>>(X, Y, (float*)d_out, nblk, 1.0 / n_out);
}

// round 7
// speedup vs baseline: 1.0024x; 1.0024x over previous
#include <cuda_runtime.h>
#include <cstdint>

typedef unsigned long long ull;

#define IMG_W 512
#define ROWB  2048    // bytes per image row
#define OUT_W 507
#define NSTR  3       // strips per image
#define STRIP 169     // output rows per strip (3*169 = 507 exact)
#define NROWS 174     // input rows per strip (STRIP + 5), divisible by 6
#define NB_MM 1184

// ---------------- device-global scratch (no allocs) --------------------------
__device__ float    g_mn[NB_MM], g_mx[NB_MM];
__device__ float    g_part[512];
__device__ unsigned g_done;          // zero-init; last block resets each run

// ---------------- packed f32x2 helpers (sm_103a) ------------------------------
static __device__ __forceinline__ ull pk2(float a, float b){
    ull r; asm("mov.b64 %0, {%1, %2};" : "=l"(r) : "f"(a), "f"(b)); return r;
}
static __device__ __forceinline__ ull mul2(ull a, ull b){
    ull r; asm("mul.rn.f32x2 %0, %1, %2;" : "=l"(r) : "l"(a), "l"(b)); return r;
}
static __device__ __forceinline__ ull add2(ull a, ull b){
    ull r; asm("add.rn.f32x2 %0, %1, %2;" : "=l"(r) : "l"(a), "l"(b)); return r;
}
static __device__ __forceinline__ ull fma2(ull a, ull b, ull c){
    ull r; asm("fma.rn.f32x2 %0, %1, %2, %3;" : "=l"(r) : "l"(a), "l"(b), "l"(c)); return r;
}
static __device__ __forceinline__ float lo2(ull a){ return __uint_as_float((unsigned)a); }
static __device__ __forceinline__ float hi2(ull a){ return __uint_as_float((unsigned)(a >> 32)); }
static __device__ __forceinline__ void pref2(const void* p){
    asm volatile("prefetch.global.L2 [%0];" :: "l"(p));
}

// ---------------- gaussian weights (w_size=6, sigma=1.5, normalized) ---------
#define GW0 0.03802585f
#define GW1 0.11551231f
#define GW2 0.22498725f
#define GW3 0.28097506f

// ---------------- min/max partials kernel -------------------------------------
__global__ void k_minmax(const float4* __restrict__ x, int n4){
    float mn = 3.4028235e38f, mx = -3.4028235e38f;
    int stride = gridDim.x * blockDim.x;
    for (int i = blockIdx.x * blockDim.x + threadIdx.x; i < n4; i += stride){
        float4 v = x[i];
        mn = fminf(mn, fminf(fminf(v.x, v.y), fminf(v.z, v.w)));
        mx = fmaxf(mx, fmaxf(fmaxf(v.x, v.y), fmaxf(v.z, v.w)));
    }
    #pragma unroll
    for (int o = 16; o > 0; o >>= 1){
        mn = fminf(mn, __shfl_xor_sync(0xFFFFFFFFu, mn, o));
        mx = fmaxf(mx, __shfl_xor_sync(0xFFFFFFFFu, mx, o));
    }
    __shared__ float smn[8], smx[8];
    int wid = threadIdx.x >> 5, lane = threadIdx.x & 31;
    if (lane == 0){ smn[wid] = mn; smx[wid] = mx; }
    __syncthreads();
    if (threadIdx.x == 0){
        mn = smn[0]; mx = smx[0];
        #pragma unroll
        for (int w = 1; w < 8; ++w){ mn = fminf(mn, smn[w]); mx = fmaxf(mx, smx[w]); }
        g_mn[blockIdx.x] = mn;
        g_mx[blockIdx.x] = mx;
    }
}

// Mixed even/odd 6-tap horizontal conv over packed lanes (cols c, c+1).
// A=(f0,f1) B=(f2,f3) C=(f4,f5) D=(f6,f7) aligned pairs.
// Even taps (0,2,4): packed FMA2 with broadcast weights -> pairs used as-is.
// Odd taps (1,3,5): scalar FFMA-imm on free register halves. No shifted pk2.
#define HCONV(DST, A, B, C, D) do { \
    ull d_ = mul2((A), W0b); \
    d_ = fma2((B), W2b, d_); \
    d_ = fma2((C), W2b, d_); \
    float dl_ = lo2(d_), dh_ = hi2(d_); \
    dl_ = fmaf(hi2(A), GW1, dl_); \
    dl_ = fmaf(hi2(B), GW3, dl_); \
    dl_ = fmaf(hi2(C), GW1, dl_); \
    dh_ = fmaf(lo2(B), GW1, dh_); \
    dh_ = fmaf(lo2(C), GW3, dh_); \
    dh_ = fmaf(lo2(D), GW1, dh_); \
    DST = pk2(dl_, dh_); \
} while(0)

// Vertical 6-tap packed MAC (broadcast weights, no shifts)
#define VMAC(d, v0, v1, v2, v3, v4, v5) \
    d = mul2((v0), W0b); d = fma2((v1), W1b, d); d = fma2((v2), W2b, d); \
    d = fma2((v3), W3b, d); d = fma2((v4), W2b, d); d = fma2((v5), W1b, d)

// load one input row (both tensors) into ull set S. OFF = compile-time byte offset
// from the group base pointers xr/yr (which track row i6+2).
#define LOADROW(S, OFF) do { \
    rx[S][0] = *(const ull*)(xr + (OFF)); \
    rx[S][1] = *(const ull*)(xr + (OFF) + d1); \
    rx[S][2] = *(const ull*)(xr + (OFF) + d2); \
    rx[S][3] = *(const ull*)(xr + (OFF) + d3); \
    ry[S][0] = *(const ull*)(yr + (OFF)); \
    ry[S][1] = *(const ull*)(yr + (OFF) + d1); \
    ry[S][2] = *(const ull*)(yr + (OFF) + d2); \
    ry[S][3] = *(const ull*)(yr + (OFF) + d3); \
} while(0)

// One row-step. P literal 0..5. DOOUT/DOLOAD/DOPREF compile-time 0/1.
#define ROW_STEP(P, DOOUT, DOLOAD, DOPREF) do { \
    if (DOPREF){ pref2(xp + (P)*ROWB); pref2(yp + (P)*ROWB); } \
    if (DOLOAD){ LOADROW(((P)+2)%3, (P)*ROWB); } \
    { \
        ull xA_ = rx[(P)%3][0], xB_ = rx[(P)%3][1], xC_ = rx[(P)%3][2], xD_ = rx[(P)%3][3]; \
        ull yA_ = ry[(P)%3][0], yB_ = ry[(P)%3][1], yC_ = ry[(P)%3][2], yD_ = ry[(P)%3][3]; \
        ull pA_ = fma2(yA_, yA_, mul2(xA_, xA_)); \
        ull pB_ = fma2(yB_, yB_, mul2(xB_, xB_)); \
        ull pC_ = fma2(yC_, yC_, mul2(xC_, xC_)); \
        ull pD_ = fma2(yD_, yD_, mul2(xD_, xD_)); \
        ull qA_ = mul2(xA_, yA_), qB_ = mul2(xB_, yB_); \
        ull qC_ = mul2(xC_, yC_), qD_ = mul2(xD_, yD_); \
        HCONV(ring[(P)][0], xA_, xB_, xC_, xD_); \
        HCONV(ring[(P)][1], yA_, yB_, yC_, yD_); \
        HCONV(ring[(P)][2], pA_, pB_, pC_, pD_); \
        HCONV(ring[(P)][3], qA_, qB_, qC_, qD_); \
    } \
    if (DOOUT){ \
        ull v0_, v1_, v2_, v3_; \
        VMAC(v0_, ring[((P)+1)%6][0], ring[((P)+2)%6][0], ring[((P)+3)%6][0], ring[((P)+4)%6][0], ring[((P)+5)%6][0], ring[(P)][0]); \
        VMAC(v1_, ring[((P)+1)%6][1], ring[((P)+2)%6][1], ring[((P)+3)%6][1], ring[((P)+4)%6][1], ring[((P)+5)%6][1], ring[(P)][1]); \
        VMAC(v2_, ring[((P)+1)%6][2], ring[((P)+2)%6][2], ring[((P)+3)%6][2], ring[((P)+4)%6][2], ring[((P)+5)%6][2], ring[(P)][2]); \
        VMAC(v3_, ring[((P)+1)%6][3], ring[((P)+2)%6][3], ring[((P)+3)%6][3], ring[((P)+4)%6][3], ring[((P)+5)%6][3], ring[(P)][3]); \
        ull mu12_ = mul2(v0_, v1_); \
        ull msum_ = fma2(v1_, v1_, mul2(v0_, v0_)); \
        ull t1_ = fma2(mu12_, NTWO, fma2(v3_, TWO, C2p)); \
        ull t2_ = fma2(msum_, NONE, add2(v2_, C2p)); \
        ull num_ = mul2(fma2(mu12_, TWO, C1p), t1_); \
        ull den_ = mul2(add2(msum_, C1p), t2_); \
        float nl_ = lo2(num_), nh_ = hi2(num_); \
        float dl_ = lo2(den_), dh_ = hi2(den_); \
        if (hi_ok)      acc += __fdividef(fmaf(nl_, dh_, nh_ * dl_), dl_ * dh_); \
        else if (lo_ok) acc += __fdividef(nl_, dl_); \
    } \
} while(0)

__global__ void __launch_bounds__(256, 2)
k_ssim(const float* __restrict__ X, const float* __restrict__ Y,
       float* __restrict__ out, int nblk, double inv_n){
    __shared__ float    smn[8], smx[8], sC[2];
    __shared__ double   sd[8];
    __shared__ unsigned s_tick;

    const int tid   = threadIdx.x;
    const int c0    = tid * 2;
    const int bx    = blockIdx.x;
    const int strip = bx % NSTR;
    const int img   = bx / NSTR;
    const int base  = strip * STRIP;
    const float* xi = X + (size_t)img * (IMG_W * IMG_W);
    const float* yi = Y + (size_t)img * (IMG_W * IMG_W);
    const bool lo_ok = (c0     < OUT_W);
    const bool hi_ok = (c0 + 1 < OUT_W);

    // clamped column byte deltas (edge threads read in-bounds garbage; masked)
    const int o0 = c0;
    const int d1 = (min(c0 + 2, 510) - c0) * 4;
    const int d2 = (min(c0 + 4, 510) - c0) * 4;
    const int d3 = (min(c0 + 6, 510) - c0) * 4;

    // group base pointers: xr/yr -> LDG row (group_i+2); xp/yp -> prefetch row (group_i+6)
    const char* xr = (const char*)(xi + (size_t)(base + 2) * IMG_W + o0);
    const char* yr = (const char*)(yi + (size_t)(base + 2) * IMG_W + o0);
    const char* xp = (const char*)(xi + (size_t)(base + 6) * IMG_W + o0);
    const char* yp = (const char*)(yi + (size_t)(base + 6) * IMG_W + o0);

    // ---- reduce min/max partials -> C1, C2 ----
    {
        float mn = 3.4028235e38f, mx = -3.4028235e38f;
        for (int i = tid; i < NB_MM; i += 256){
            mn = fminf(mn, g_mn[i]);
            mx = fmaxf(mx, g_mx[i]);
        }
        #pragma unroll
        for (int o = 16; o > 0; o >>= 1){
            mn = fminf(mn, __shfl_xor_sync(0xFFFFFFFFu, mn, o));
            mx = fmaxf(mx, __shfl_xor_sync(0xFFFFFFFFu, mx, o));
        }
        int wid = tid >> 5, lane = tid & 31;
        if (lane == 0){ smn[wid] = mn; smx[wid] = mx; }
    }

    // register pipeline: 3 rotating row sets (u64 aligned pairs)
    ull rx[3][4], ry[3][4];
    LOADROW(0, -2*ROWB);           // row base
    LOADROW(1, -1*ROWB);           // row base+1
    #pragma unroll
    for (int r = -4; r < 0; ++r){  // L2-prefetch rows base+2..base+5
        pref2(xp + r*ROWB);
        pref2(yp + r*ROWB);
    }

    __syncthreads();
    if (tid == 0){
        float mn = smn[0], mx = smx[0];
        #pragma unroll
        for (int w = 1; w < 8; ++w){ mn = fminf(mn, smn[w]); mx = fmaxf(mx, smx[w]); }
        float Ldyn = (mx > 128.0f ? 255.0f : 1.0f) - (mn < -0.5f ? -1.0f : 0.0f);
        sC[0] = (0.01f * Ldyn) * (0.01f * Ldyn);
        sC[1] = (0.03f * Ldyn) * (0.03f * Ldyn);
    }
    __syncthreads();

    const float C1 = sC[0], C2 = sC[1];
    const ull W0b = pk2(GW0, GW0), W1b = pk2(GW1, GW1);
    const ull W2b = pk2(GW2, GW2), W3b = pk2(GW3, GW3);
    const ull C1p = pk2(C1, C1),   C2p = pk2(C2, C2);
    const ull TWO = pk2(2.0f, 2.0f), NTWO = pk2(-2.0f, -2.0f), NONE = pk2(-1.0f, -1.0f);

    ull ring[6][4];
    float acc = 0.0f;

    // ---- group 0 (rows 0..5): warm-up, first output at row 5 ----
    ROW_STEP(0, 0, 1, 1);
    ROW_STEP(1, 0, 1, 1);
    ROW_STEP(2, 0, 1, 1);
    ROW_STEP(3, 0, 1, 1);
    ROW_STEP(4, 0, 1, 1);
    ROW_STEP(5, 1, 1, 1);
    xr += 6*ROWB; yr += 6*ROWB; xp += 6*ROWB; yp += 6*ROWB;

    // ---- middle groups (rows 6..167): fully clean, no predicates ----
    #pragma unroll 1
    for (int g = 0; g < 27; ++g){
        ROW_STEP(0, 1, 1, 1);
        ROW_STEP(1, 1, 1, 1);
        ROW_STEP(2, 1, 1, 1);
        ROW_STEP(3, 1, 1, 1);
        ROW_STEP(4, 1, 1, 1);
        ROW_STEP(5, 1, 1, 1);
        xr += 6*ROWB; yr += 6*ROWB; xp += 6*ROWB; yp += 6*ROWB;
    }

    // ---- tail group (rows 168..173): loads stop at row 173, no prefetch ----
    ROW_STEP(0, 1, 1, 0);   // loads row 170
    ROW_STEP(1, 1, 1, 0);   // loads row 171
    ROW_STEP(2, 1, 1, 0);   // loads row 172
    ROW_STEP(3, 1, 1, 0);   // loads row 173 (last input row)
    ROW_STEP(4, 1, 0, 0);
    ROW_STEP(5, 1, 0, 0);

    // ---- block reduction -> partial; last block finishes ----
    #pragma unroll
    for (int o = 16; o > 0; o >>= 1)
        acc += __shfl_xor_sync(0xFFFFFFFFu, acc, o);
    const int wid = tid >> 5, lane = tid & 31;
    if (lane == 0) smn[wid] = acc;
    __syncthreads();
    if (tid == 0){
        float s = smn[0];
        #pragma unroll
        for (int w = 1; w < 8; ++w) s += smn[w];
        g_part[bx] = s;
        __threadfence();
        s_tick = atomicAdd(&g_done, 1u);
    }
    __syncthreads();

    if (s_tick == (unsigned)(nblk - 1)){
        double s = 0.0;
        for (int i = tid; i < nblk; i += 256) s += (double)g_part[i];
        #pragma unroll
        for (int o = 16; o > 0; o >>= 1)
            s += __shfl_xor_sync(0xFFFFFFFFu, s, o);
        if (lane == 0) sd[wid] = s;
        __syncthreads();
        if (tid == 0){
            double t = 0.0;
            #pragma unroll
            for (int w = 0; w < 8; ++w) t += sd[w];
            out[0] = (float)((1.0 - t * inv_n) * 0.5);
            g_done = 0u;   // reset for next graph replay
        }
    }
}

// ---------------- launch --------------------------------------------------------
extern "C" void kernel_launch(void* const* d_in, const int* in_sizes, int n_in,
                              void* d_out, int out_size){
    const float* X = (const float*)d_in[0];  // y_pred
    const float* Y = (const float*)d_in[1];  // y_true

    const int nelem = in_sizes[0];
    const int nimg  = nelem / (IMG_W * IMG_W);
    const int nblk  = NSTR * nimg;
    const double n_out = (double)nimg * (double)OUT_W * (double)OUT_W;

    k_minmax<<<NB_MM, 256>>>((const float4*)X, nelem / 4);
    k_ssim<<<nblk, 256>>>(X, Y, (float*)d_out, nblk, 1.0 / n_out);
}

// round 8
// speedup vs baseline: 1.0855x; 1.0829x over previous
#include <cuda_runtime.h>
#include <cstdint>

typedef unsigned long long ull;

#define IMG_W 512
#define OUT_W 507
#define NSTR  3       // strips per image
#define STRIP 169     // output rows per strip (3*169 = 507 exact)
#define NROWS 174     // input rows per strip (STRIP + 5), divisible by 6
#define NB_MM 1184

// ---------------- device-global scratch (no allocs) --------------------------
__device__ float    g_mn[NB_MM], g_mx[NB_MM];
__device__ float    g_part[512];
__device__ unsigned g_done;          // zero-init; last block resets each run

// ---------------- packed f32x2 helpers (sm_103a) ------------------------------
static __device__ __forceinline__ ull pk2(float a, float b){
    ull r; asm("mov.b64 %0, {%1, %2};" : "=l"(r) : "f"(a), "f"(b)); return r;
}
static __device__ __forceinline__ ull mul2(ull a, ull b){
    ull r; asm("mul.rn.f32x2 %0, %1, %2;" : "=l"(r) : "l"(a), "l"(b)); return r;
}
static __device__ __forceinline__ ull add2(ull a, ull b){
    ull r; asm("add.rn.f32x2 %0, %1, %2;" : "=l"(r) : "l"(a), "l"(b)); return r;
}
static __device__ __forceinline__ ull fma2(ull a, ull b, ull c){
    ull r; asm("fma.rn.f32x2 %0, %1, %2, %3;" : "=l"(r) : "l"(a), "l"(b), "l"(c)); return r;
}
static __device__ __forceinline__ float lo2(ull a){ return __uint_as_float((unsigned)a); }
static __device__ __forceinline__ float hi2(ull a){ return __uint_as_float((unsigned)(a >> 32)); }
static __device__ __forceinline__ void pref2(const float* p){
    asm volatile("prefetch.global.L2 [%0];" :: "l"(p));
}

// ---------------- gaussian weights (w_size=6, sigma=1.5, normalized) ---------
#define GW0 0.03802585f
#define GW1 0.11551231f
#define GW2 0.22498725f
#define GW3 0.28097506f

// ---------------- min/max partials kernel (MLP-4 unrolled) --------------------
__global__ void k_minmax(const float4* __restrict__ x, int n4){
    float mn0 = 3.4028235e38f, mx0 = -3.4028235e38f;
    float mn1 = mn0, mx1 = mx0, mn2 = mn0, mx2 = mx0, mn3 = mn0, mx3 = mx0;
    const int nt = gridDim.x * blockDim.x;
    const int t  = blockIdx.x * blockDim.x + threadIdx.x;
    int i = t;
    for (; i + 3*nt < n4; i += 4*nt){
        float4 a = x[i];
        float4 b = x[i + nt];
        float4 c = x[i + 2*nt];
        float4 d = x[i + 3*nt];
        mn0 = fminf(mn0, fminf(fminf(a.x, a.y), fminf(a.z, a.w)));
        mx0 = fmaxf(mx0, fmaxf(fmaxf(a.x, a.y), fmaxf(a.z, a.w)));
        mn1 = fminf(mn1, fminf(fminf(b.x, b.y), fminf(b.z, b.w)));
        mx1 = fmaxf(mx1, fmaxf(fmaxf(b.x, b.y), fmaxf(b.z, b.w)));
        mn2 = fminf(mn2, fminf(fminf(c.x, c.y), fminf(c.z, c.w)));
        mx2 = fmaxf(mx2, fmaxf(fmaxf(c.x, c.y), fmaxf(c.z, c.w)));
        mn3 = fminf(mn3, fminf(fminf(d.x, d.y), fminf(d.z, d.w)));
        mx3 = fmaxf(mx3, fmaxf(fmaxf(d.x, d.y), fmaxf(d.z, d.w)));
    }
    for (; i < n4; i += nt){
        float4 a = x[i];
        mn0 = fminf(mn0, fminf(fminf(a.x, a.y), fminf(a.z, a.w)));
        mx0 = fmaxf(mx0, fmaxf(fmaxf(a.x, a.y), fmaxf(a.z, a.w)));
    }
    float mn = fminf(fminf(mn0, mn1), fminf(mn2, mn3));
    float mx = fmaxf(fmaxf(mx0, mx1), fmaxf(mx2, mx3));
    #pragma unroll
    for (int o = 16; o > 0; o >>= 1){
        mn = fminf(mn, __shfl_xor_sync(0xFFFFFFFFu, mn, o));
        mx = fmaxf(mx, __shfl_xor_sync(0xFFFFFFFFu, mx, o));
    }
    __shared__ float smn[8], smx[8];
    int wid = threadIdx.x >> 5, lane = threadIdx.x & 31;
    if (lane == 0){ smn[wid] = mn; smx[wid] = mx; }
    __syncthreads();
    if (threadIdx.x == 0){
        mn = smn[0]; mx = smx[0];
        #pragma unroll
        for (int w = 1; w < 8; ++w){ mn = fminf(mn, smn[w]); mx = fmaxf(mx, smx[w]); }
        g_mn[blockIdx.x] = mn;
        g_mx[blockIdx.x] = mx;
    }
}

// 6-tap packed MAC: taps [GW0,GW1,GW2,GW3,GW2,GW1]
#define HMAC(d, v0, v1, v2, v3, v4, v5) \
    d = mul2((v0), W0); d = fma2((v1), W1, d); d = fma2((v2), W2, d); \
    d = fma2((v3), W3, d); d = fma2((v4), W2, d); d = fma2((v5), W1, d)

// load one input row (both tensors) into register set S (S literal 0..2)
#define LOADROW(S, XR, YR) do { \
    rx[S][0] = *(const float2*)(XR); \
    rx[S][1] = *(const float2*)((const char*)(XR) + d1); \
    rx[S][2] = *(const float2*)((const char*)(XR) + d2); \
    rx[S][3] = *(const float2*)((const char*)(XR) + d3); \
    ry[S][0] = *(const float2*)(YR); \
    ry[S][1] = *(const float2*)((const char*)(YR) + d1); \
    ry[S][2] = *(const float2*)((const char*)(YR) + d2); \
    ry[S][3] = *(const float2*)((const char*)(YR) + d3); \
} while(0)

// One row-step. P literal 0..5. DOOUT/DOLOAD/DOPREF compile-time 0/1.
#define ROW_STEP(P, DOOUT, DOLOAD, DOPREF) do { \
    if (DOPREF){ pref2(xp); pref2(yp); xp += IMG_W; yp += IMG_W; } \
    if (DOLOAD){ LOADROW(((P)+2)%3, xr, yr); xr += IMG_W; yr += IMG_W; } \
    { \
        float2 X0_ = rx[(P)%3][0], X1_ = rx[(P)%3][1], X2_ = rx[(P)%3][2], X3_ = rx[(P)%3][3]; \
        float2 Y0_ = ry[(P)%3][0], Y1_ = ry[(P)%3][1], Y2_ = ry[(P)%3][2], Y3_ = ry[(P)%3][3]; \
        ull xp0_ = pk2(X0_.x, X0_.y), xp1_ = pk2(X1_.x, X1_.y); \
        ull xp2_ = pk2(X2_.x, X2_.y), xp3_ = pk2(X3_.x, X3_.y); \
        ull yp0_ = pk2(Y0_.x, Y0_.y), yp1_ = pk2(Y1_.x, Y1_.y); \
        ull yp2_ = pk2(Y2_.x, Y2_.y), yp3_ = pk2(Y3_.x, Y3_.y); \
        ull pp0_ = fma2(yp0_, yp0_, mul2(xp0_, xp0_)); \
        ull pp1_ = fma2(yp1_, yp1_, mul2(xp1_, xp1_)); \
        ull pp2_ = fma2(yp2_, yp2_, mul2(xp2_, xp2_)); \
        ull pp3_ = fma2(yp3_, yp3_, mul2(xp3_, xp3_)); \
        ull qq0_ = mul2(xp0_, yp0_), qq1_ = mul2(xp1_, yp1_); \
        ull qq2_ = mul2(xp2_, yp2_), qq3_ = mul2(xp3_, yp3_); \
        { ull d_; HMAC(d_, xp0_, pk2(X0_.y, X1_.x), xp1_, pk2(X1_.y, X2_.x), xp2_, pk2(X2_.y, X3_.x)); ring[(P)][0] = d_; } \
        { ull d_; HMAC(d_, yp0_, pk2(Y0_.y, Y1_.x), yp1_, pk2(Y1_.y, Y2_.x), yp2_, pk2(Y2_.y, Y3_.x)); ring[(P)][1] = d_; } \
        { ull d_; HMAC(d_, pp0_, pk2(hi2(pp0_), lo2(pp1_)), pp1_, pk2(hi2(pp1_), lo2(pp2_)), pp2_, pk2(hi2(pp2_), lo2(pp3_))); ring[(P)][2] = d_; } \
        { ull d_; HMAC(d_, qq0_, pk2(hi2(qq0_), lo2(qq1_)), qq1_, pk2(hi2(qq1_), lo2(qq2_)), qq2_, pk2(hi2(qq2_), lo2(qq3_))); ring[(P)][3] = d_; } \
    } \
    if (DOOUT){ \
        ull v0_, v1_, v2_, v3_; \
        HMAC(v0_, ring[((P)+1)%6][0], ring[((P)+2)%6][0], ring[((P)+3)%6][0], ring[((P)+4)%6][0], ring[((P)+5)%6][0], ring[(P)][0]); \
        HMAC(v1_, ring[((P)+1)%6][1], ring[((P)+2)%6][1], ring[((P)+3)%6][1], ring[((P)+4)%6][1], ring[((P)+5)%6][1], ring[(P)][1]); \
        HMAC(v2_, ring[((P)+1)%6][2], ring[((P)+2)%6][2], ring[((P)+3)%6][2], ring[((P)+4)%6][2], ring[((P)+5)%6][2], ring[(P)][2]); \
        HMAC(v3_, ring[((P)+1)%6][3], ring[((P)+2)%6][3], ring[((P)+3)%6][3], ring[((P)+4)%6][3], ring[((P)+5)%6][3], ring[(P)][3]); \
        ull mu12_ = mul2(v0_, v1_); \
        ull msum_ = fma2(v1_, v1_, mul2(v0_, v0_)); \
        ull t1_ = fma2(mu12_, NTWO, fma2(v3_, TWO, C2p)); \
        ull t2_ = fma2(msum_, NONE, add2(v2_, C2p)); \
        ull num_ = mul2(fma2(mu12_, TWO, C1p), t1_); \
        ull den_ = mul2(add2(msum_, C1p), t2_); \
        if (lo_ok) acc0 += __fdividef(lo2(num_), lo2(den_)); \
        if (hi_ok) acc1 += __fdividef(hi2(num_), hi2(den_)); \
    } \
} while(0)

__global__ void __launch_bounds__(256, 2)
k_ssim(const float* __restrict__ X, const float* __restrict__ Y,
       float* __restrict__ out, int nblk, double inv_n){
    __shared__ float    smn[8], smx[8], sC[2];
    __shared__ double   sd[8];
    __shared__ unsigned s_tick;

    const int tid   = threadIdx.x;
    const int c0    = tid * 2;
    const int bx    = blockIdx.x;
    const int strip = bx % NSTR;
    const int img   = bx / NSTR;
    const int base  = strip * STRIP;
    const float* xi = X + (size_t)img * (IMG_W * IMG_W);
    const float* yi = Y + (size_t)img * (IMG_W * IMG_W);
    const bool lo_ok = (c0     < OUT_W);
    const bool hi_ok = (c0 + 1 < OUT_W);

    // clamped column byte deltas (edge threads read in-bounds garbage; masked)
    const int o0 = c0;
    const int d1 = (min(c0 + 2, 510) - c0) * 4;
    const int d2 = (min(c0 + 4, 510) - c0) * 4;
    const int d3 = (min(c0 + 6, 510) - c0) * 4;

    // running row pointers: xr/yr -> next LDG row (base+2); xp/yp -> prefetch row (base+6)
    const float* xr = xi + (size_t)(base + 2) * IMG_W + o0;
    const float* yr = yi + (size_t)(base + 2) * IMG_W + o0;
    const float* xp = xi + (size_t)(base + 6) * IMG_W + o0;
    const float* yp = yi + (size_t)(base + 6) * IMG_W + o0;

    // ---- reduce min/max partials -> C1, C2 ----
    {
        float mn = 3.4028235e38f, mx = -3.4028235e38f;
        for (int i = tid; i < NB_MM; i += 256){
            mn = fminf(mn, g_mn[i]);
            mx = fmaxf(mx, g_mx[i]);
        }
        #pragma unroll
        for (int o = 16; o > 0; o >>= 1){
            mn = fminf(mn, __shfl_xor_sync(0xFFFFFFFFu, mn, o));
            mx = fmaxf(mx, __shfl_xor_sync(0xFFFFFFFFu, mx, o));
        }
        int wid = tid >> 5, lane = tid & 31;
        if (lane == 0){ smn[wid] = mn; smx[wid] = mx; }
    }

    // register pipeline: 3 rotating row sets
    float2 rx[3][4], ry[3][4];
    {
        const float* x0 = xi + (size_t)base * IMG_W + o0;
        const float* y0 = yi + (size_t)base * IMG_W + o0;
        LOADROW(0, x0, y0);
        LOADROW(1, x0 + IMG_W, y0 + IMG_W);
        #pragma unroll
        for (int r = 2; r < 6; ++r){
            pref2(x0 + (size_t)r * IMG_W);
            pref2(y0 + (size_t)r * IMG_W);
        }
    }

    __syncthreads();
    if (tid == 0){
        float mn = smn[0], mx = smx[0];
        #pragma unroll
        for (int w = 1; w < 8; ++w){ mn = fminf(mn, smn[w]); mx = fmaxf(mx, smx[w]); }
        float Ldyn = (mx > 128.0f ? 255.0f : 1.0f) - (mn < -0.5f ? -1.0f : 0.0f);
        sC[0] = (0.01f * Ldyn) * (0.01f * Ldyn);
        sC[1] = (0.03f * Ldyn) * (0.03f * Ldyn);
    }
    __syncthreads();

    const float C1 = sC[0], C2 = sC[1];
    const ull W0  = pk2(GW0, GW0), W1 = pk2(GW1, GW1);
    const ull W2  = pk2(GW2, GW2), W3 = pk2(GW3, GW3);
    const ull C1p = pk2(C1, C1),   C2p = pk2(C2, C2);
    const ull TWO = pk2(2.0f, 2.0f), NTWO = pk2(-2.0f, -2.0f), NONE = pk2(-1.0f, -1.0f);

    ull ring[6][4];
    float acc0 = 0.0f, acc1 = 0.0f;

    // ---- group 0 (rows 0..5): warm-up, first output at row 5 ----
    ROW_STEP(0, 0, 1, 1);
    ROW_STEP(1, 0, 1, 1);
    ROW_STEP(2, 0, 1, 1);
    ROW_STEP(3, 0, 1, 1);
    ROW_STEP(4, 0, 1, 1);
    ROW_STEP(5, 1, 1, 1);

    // ---- middle groups (rows 6..167): fully clean, no predicates ----
    #pragma unroll 1
    for (int i6 = 6; i6 < 168; i6 += 6){
        ROW_STEP(0, 1, 1, 1);
        ROW_STEP(1, 1, 1, 1);
        ROW_STEP(2, 1, 1, 1);
        ROW_STEP(3, 1, 1, 1);
        ROW_STEP(4, 1, 1, 1);
        ROW_STEP(5, 1, 1, 1);
    }

    // ---- tail group (rows 168..173): loads stop at row 173, no prefetch ----
    ROW_STEP(0, 1, 1, 0);   // loads row 170
    ROW_STEP(1, 1, 1, 0);   // loads row 171
    ROW_STEP(2, 1, 1, 0);   // loads row 172
    ROW_STEP(3, 1, 1, 0);   // loads row 173 (last input row)
    ROW_STEP(4, 1, 0, 0);
    ROW_STEP(5, 1, 0, 0);

    // ---- block reduction -> partial; last block finishes ----
    float acc = acc0 + acc1;
    #pragma unroll
    for (int o = 16; o > 0; o >>= 1)
        acc += __shfl_xor_sync(0xFFFFFFFFu, acc, o);
    const int wid = tid >> 5, lane = tid & 31;
    if (lane == 0) smn[wid] = acc;
    __syncthreads();
    if (tid == 0){
        float s = smn[0];
        #pragma unroll
        for (int w = 1; w < 8; ++w) s += smn[w];
        g_part[bx] = s;
        __threadfence();
        s_tick = atomicAdd(&g_done, 1u);
    }
    __syncthreads();

    if (s_tick == (unsigned)(nblk - 1)){
        double s = 0.0;
        for (int i = tid; i < nblk; i += 256) s += (double)g_part[i];
        #pragma unroll
        for (int o = 16; o > 0; o >>= 1)
            s += __shfl_xor_sync(0xFFFFFFFFu, s, o);
        if (lane == 0) sd[wid] = s;
        __syncthreads();
        if (tid == 0){
            double t = 0.0;
            #pragma unroll
            for (int w = 0; w < 8; ++w) t += sd[w];
            out[0] = (float)((1.0 - t * inv_n) * 0.5);
            g_done = 0u;   // reset for next graph replay
        }
    }
}

// ---------------- launch --------------------------------------------------------
extern "C" void kernel_launch(void* const* d_in, const int* in_sizes, int n_in,
                              void* d_out, int out_size){
    const float* X = (const float*)d_in[0];  // y_pred
    const float* Y = (const float*)d_in[1];  // y_true

    const int nelem = in_sizes[0];
    const int nimg  = nelem / (IMG_W * IMG_W);
    const int nblk  = NSTR * nimg;
    const double n_out = (double)nimg * (double)OUT_W * (double)OUT_W;

    k_minmax<<<NB_MM, 256>>>((const float4*)X, nelem / 4);
    k_ssim<<<nblk, 256>>>(X, Y, (float*)d_out, nblk, 1.0 / n_out);
}

// round 9
// speedup vs baseline: 1.1579x; 1.0667x over previous
#include <cuda_runtime.h>
#include <cstdint>

typedef unsigned long long ull;

#define IMG_W 512
#define OUT_W 507
#define NSTR  3       // strips per image
#define STRIP 169     // output rows per strip (3*169 = 507 exact)
#define NROWS 174     // input rows per strip (STRIP + 5), divisible by 6
#define NB_MM 1184
#define SEGF  72      // floats per warp row segment (64 + 6 halo + 2 pad)

// ---------------- device-global scratch (no allocs) --------------------------
__device__ float    g_mn[NB_MM], g_mx[NB_MM];
__device__ float    g_part[512];
__device__ unsigned g_done;          // zero-init; last block resets each run

// ---------------- packed f32x2 helpers (sm_103a) ------------------------------
static __device__ __forceinline__ ull pk2(float a, float b){
    ull r; asm("mov.b64 %0, {%1, %2};" : "=l"(r) : "f"(a), "f"(b)); return r;
}
static __device__ __forceinline__ ull mul2(ull a, ull b){
    ull r; asm("mul.rn.f32x2 %0, %1, %2;" : "=l"(r) : "l"(a), "l"(b)); return r;
}
static __device__ __forceinline__ ull add2(ull a, ull b){
    ull r; asm("add.rn.f32x2 %0, %1, %2;" : "=l"(r) : "l"(a), "l"(b)); return r;
}
static __device__ __forceinline__ ull fma2(ull a, ull b, ull c){
    ull r; asm("fma.rn.f32x2 %0, %1, %2, %3;" : "=l"(r) : "l"(a), "l"(b), "l"(c)); return r;
}
static __device__ __forceinline__ float lo2(ull a){ return __uint_as_float((unsigned)a); }
static __device__ __forceinline__ float hi2(ull a){ return __uint_as_float((unsigned)(a >> 32)); }

static __device__ __forceinline__ void cpa16(unsigned dst, const void* src){
    asm volatile("cp.async.ca.shared.global [%0], [%1], 16;" :: "r"(dst), "l"(src) : "memory");
}
static __device__ __forceinline__ void cpa_commit(){
    asm volatile("cp.async.commit_group;" ::: "memory");
}
static __device__ __forceinline__ void cpa_wait2(){
    asm volatile("cp.async.wait_group 2;" ::: "memory");
}

// ---------------- gaussian weights (w_size=6, sigma=1.5, normalized) ---------
#define GW0 0.03802585f
#define GW1 0.11551231f
#define GW2 0.22498725f
#define GW3 0.28097506f

// ---------------- min/max partials kernel -------------------------------------
__global__ void k_minmax(const float4* __restrict__ x, int n4){
    float mn = 3.4028235e38f, mx = -3.4028235e38f;
    int stride = gridDim.x * blockDim.x;
    for (int i = blockIdx.x * blockDim.x + threadIdx.x; i < n4; i += stride){
        float4 v = x[i];
        mn = fminf(mn, fminf(fminf(v.x, v.y), fminf(v.z, v.w)));
        mx = fmaxf(mx, fmaxf(fmaxf(v.x, v.y), fmaxf(v.z, v.w)));
    }
    #pragma unroll
    for (int o = 16; o > 0; o >>= 1){
        mn = fminf(mn, __shfl_xor_sync(0xFFFFFFFFu, mn, o));
        mx = fmaxf(mx, __shfl_xor_sync(0xFFFFFFFFu, mx, o));
    }
    __shared__ float smn[8], smx[8];
    int wid = threadIdx.x >> 5, lane = threadIdx.x & 31;
    if (lane == 0){ smn[wid] = mn; smx[wid] = mx; }
    __syncthreads();
    if (threadIdx.x == 0){
        mn = smn[0]; mx = smx[0];
        #pragma unroll
        for (int w = 1; w < 8; ++w){ mn = fminf(mn, smn[w]); mx = fmaxf(mx, smx[w]); }
        g_mn[blockIdx.x] = mn;
        g_mx[blockIdx.x] = mx;
    }
}

// 6-tap packed MAC: taps [GW0,GW1,GW2,GW3,GW2,GW1]
#define HMAC(d, v0, v1, v2, v3, v4, v5) \
    d = mul2((v0), W0); d = fma2((v1), W1, d); d = fma2((v2), W2, d); \
    d = fma2((v3), W3, d); d = fma2((v4), W2, d); d = fma2((v5), W1, d)

// One row-step. P literal 0..5. DOLOAD compile-time 0/1.
// Loads row i+2 into smem slot (P+2)%3 via cp.async; consumes row i from slot P%3.
#define ROW_STEP(P, DOOUT, DOLOAD) do { \
    if (DOLOAD && lane18){ \
        cpa16(sxw + (((P)+2)%3)*(SEGF*4) + lane16, xsrc + (P)*2048); \
        cpa16(syw + (((P)+2)%3)*(SEGF*4) + lane16, ysrc + (P)*2048); \
    } \
    cpa_commit(); \
    cpa_wait2(); \
    __syncwarp(); \
    { \
        const float* bx_ = &swx[(P)%3][lane2]; \
        const float* by_ = &swy[(P)%3][lane2]; \
        float2 X0_ = *(const float2*)(bx_    ); \
        float2 X1_ = *(const float2*)(bx_ + 2); \
        float2 X2_ = *(const float2*)(bx_ + 4); \
        float2 X3_ = *(const float2*)(bx_ + 6); \
        float2 Y0_ = *(const float2*)(by_    ); \
        float2 Y1_ = *(const float2*)(by_ + 2); \
        float2 Y2_ = *(const float2*)(by_ + 4); \
        float2 Y3_ = *(const float2*)(by_ + 6); \
        ull xp0_ = pk2(X0_.x, X0_.y), xp1_ = pk2(X1_.x, X1_.y); \
        ull xp2_ = pk2(X2_.x, X2_.y), xp3_ = pk2(X3_.x, X3_.y); \
        ull yp0_ = pk2(Y0_.x, Y0_.y), yp1_ = pk2(Y1_.x, Y1_.y); \
        ull yp2_ = pk2(Y2_.x, Y2_.y), yp3_ = pk2(Y3_.x, Y3_.y); \
        ull pp0_ = fma2(yp0_, yp0_, mul2(xp0_, xp0_)); \
        ull pp1_ = fma2(yp1_, yp1_, mul2(xp1_, xp1_)); \
        ull pp2_ = fma2(yp2_, yp2_, mul2(xp2_, xp2_)); \
        ull pp3_ = fma2(yp3_, yp3_, mul2(xp3_, xp3_)); \
        ull qq0_ = mul2(xp0_, yp0_), qq1_ = mul2(xp1_, yp1_); \
        ull qq2_ = mul2(xp2_, yp2_), qq3_ = mul2(xp3_, yp3_); \
        { ull d_; HMAC(d_, xp0_, pk2(X0_.y, X1_.x), xp1_, pk2(X1_.y, X2_.x), xp2_, pk2(X2_.y, X3_.x)); ring[(P)][0] = d_; } \
        { ull d_; HMAC(d_, yp0_, pk2(Y0_.y, Y1_.x), yp1_, pk2(Y1_.y, Y2_.x), yp2_, pk2(Y2_.y, Y3_.x)); ring[(P)][1] = d_; } \
        { ull d_; HMAC(d_, pp0_, pk2(hi2(pp0_), lo2(pp1_)), pp1_, pk2(hi2(pp1_), lo2(pp2_)), pp2_, pk2(hi2(pp2_), lo2(pp3_))); ring[(P)][2] = d_; } \
        { ull d_; HMAC(d_, qq0_, pk2(hi2(qq0_), lo2(qq1_)), qq1_, pk2(hi2(qq1_), lo2(qq2_)), qq2_, pk2(hi2(qq2_), lo2(qq3_))); ring[(P)][3] = d_; } \
    } \
    if (DOOUT){ \
        ull v0_, v1_, v2_, v3_; \
        HMAC(v0_, ring[((P)+1)%6][0], ring[((P)+2)%6][0], ring[((P)+3)%6][0], ring[((P)+4)%6][0], ring[((P)+5)%6][0], ring[(P)][0]); \
        HMAC(v1_, ring[((P)+1)%6][1], ring[((P)+2)%6][1], ring[((P)+3)%6][1], ring[((P)+4)%6][1], ring[((P)+5)%6][1], ring[(P)][1]); \
        HMAC(v2_, ring[((P)+1)%6][2], ring[((P)+2)%6][2], ring[((P)+3)%6][2], ring[((P)+4)%6][2], ring[((P)+5)%6][2], ring[(P)][2]); \
        HMAC(v3_, ring[((P)+1)%6][3], ring[((P)+2)%6][3], ring[((P)+3)%6][3], ring[((P)+4)%6][3], ring[((P)+5)%6][3], ring[(P)][3]); \
        ull mu12_ = mul2(v0_, v1_); \
        ull msum_ = fma2(v1_, v1_, mul2(v0_, v0_)); \
        ull t1_ = fma2(mu12_, NTWO, fma2(v3_, TWO, C2p)); \
        ull t2_ = fma2(msum_, NONE, add2(v2_, C2p)); \
        ull num_ = mul2(fma2(mu12_, TWO, C1p), t1_); \
        ull den_ = mul2(add2(msum_, C1p), t2_); \
        if (lo_ok) acc0 += __fdividef(lo2(num_), lo2(den_)); \
        if (hi_ok) acc1 += __fdividef(hi2(num_), hi2(den_)); \
    } \
} while(0)

__global__ void __launch_bounds__(256, 2)
k_ssim(const float* __restrict__ X, const float* __restrict__ Y,
       float* __restrict__ out, int nblk, double inv_n){
    // warp-private row rings: [warp][slot][72 floats] per tensor
    __shared__ float s_x[8][3][SEGF];
    __shared__ float s_y[8][3][SEGF];
    __shared__ float    smn[8], smx[8], sC[2];
    __shared__ double   sd[8];
    __shared__ unsigned s_tick;

    const int tid   = threadIdx.x;
    const int wid   = tid >> 5;
    const int lane  = tid & 31;
    const int wc0   = wid * 64;            // warp's first output column
    const int c0    = wc0 + lane * 2;      // this thread's first output column
    const int lane2 = lane * 2;            // float offset within segment
    const int bx    = blockIdx.x;
    const int strip = bx % NSTR;
    const int img   = bx / NSTR;
    const int base  = strip * STRIP;
    const float* xi = X + (size_t)img * (IMG_W * IMG_W);
    const float* yi = Y + (size_t)img * (IMG_W * IMG_W);
    const bool lo_ok = (c0     < OUT_W);
    const bool hi_ok = (c0 + 1 < OUT_W);
    const bool lane18 = (lane < 18);

    // cp.async source column for this lane (16B granule), clamped to row end
    const int scol   = min(wc0 + lane * 4, 508);
    const int lane16 = lane * 16;          // byte offset within segment

    // running source byte pointers -> row (base+2)
    const char* xsrc = (const char*)(xi + (size_t)(base + 2) * IMG_W + scol);
    const char* ysrc = (const char*)(yi + (size_t)(base + 2) * IMG_W + scol);

    // smem u32 addresses of this warp's ring bases
    const unsigned sxw = (unsigned)__cvta_generic_to_shared(&s_x[wid][0][0]);
    const unsigned syw = (unsigned)__cvta_generic_to_shared(&s_y[wid][0][0]);
    const float (*swx)[SEGF] = s_x[wid];
    const float (*swy)[SEGF] = s_y[wid];

    // ---- reduce min/max partials -> C1, C2 ----
    {
        float mn = 3.4028235e38f, mx = -3.4028235e38f;
        for (int i = tid; i < NB_MM; i += 256){
            mn = fminf(mn, g_mn[i]);
            mx = fmaxf(mx, g_mx[i]);
        }
        #pragma unroll
        for (int o = 16; o > 0; o >>= 1){
            mn = fminf(mn, __shfl_xor_sync(0xFFFFFFFFu, mn, o));
            mx = fmaxf(mx, __shfl_xor_sync(0xFFFFFFFFu, mx, o));
        }
        if (lane == 0){ smn[wid] = mn; smx[wid] = mx; }
    }

    // prologue: rows base+0 -> slot 0, base+1 -> slot 1 (separate groups)
    if (lane18){
        cpa16(sxw + 0*(SEGF*4) + lane16, xsrc - 2*2048);
        cpa16(syw + 0*(SEGF*4) + lane16, ysrc - 2*2048);
    }
    cpa_commit();
    if (lane18){
        cpa16(sxw + 1*(SEGF*4) + lane16, xsrc - 1*2048);
        cpa16(syw + 1*(SEGF*4) + lane16, ysrc - 1*2048);
    }
    cpa_commit();

    __syncthreads();
    if (tid == 0){
        float mn = smn[0], mx = smx[0];
        #pragma unroll
        for (int w = 1; w < 8; ++w){ mn = fminf(mn, smn[w]); mx = fmaxf(mx, smx[w]); }
        float Ldyn = (mx > 128.0f ? 255.0f : 1.0f) - (mn < -0.5f ? -1.0f : 0.0f);
        sC[0] = (0.01f * Ldyn) * (0.01f * Ldyn);
        sC[1] = (0.03f * Ldyn) * (0.03f * Ldyn);
    }
    __syncthreads();

    const float C1 = sC[0], C2 = sC[1];
    const ull W0  = pk2(GW0, GW0), W1 = pk2(GW1, GW1);
    const ull W2  = pk2(GW2, GW2), W3 = pk2(GW3, GW3);
    const ull C1p = pk2(C1, C1),   C2p = pk2(C2, C2);
    const ull TWO = pk2(2.0f, 2.0f), NTWO = pk2(-2.0f, -2.0f), NONE = pk2(-1.0f, -1.0f);

    ull ring[6][4];
    float acc0 = 0.0f, acc1 = 0.0f;

    // ---- group 0 (rows 0..5): warm-up, first output at row 5 ----
    ROW_STEP(0, 0, 1);
    ROW_STEP(1, 0, 1);
    ROW_STEP(2, 0, 1);
    ROW_STEP(3, 0, 1);
    ROW_STEP(4, 0, 1);
    ROW_STEP(5, 1, 1);
    xsrc += 6*2048; ysrc += 6*2048;

    // ---- middle groups (rows 6..167): fully clean ----
    #pragma unroll 1
    for (int g = 0; g < 27; ++g){
        ROW_STEP(0, 1, 1);
        ROW_STEP(1, 1, 1);
        ROW_STEP(2, 1, 1);
        ROW_STEP(3, 1, 1);
        ROW_STEP(4, 1, 1);
        ROW_STEP(5, 1, 1);
        xsrc += 6*2048; ysrc += 6*2048;
    }

    // ---- tail group (rows 168..173): loads stop at row 173 ----
    ROW_STEP(0, 1, 1);   // loads row 170
    ROW_STEP(1, 1, 1);   // loads row 171
    ROW_STEP(2, 1, 1);   // loads row 172
    ROW_STEP(3, 1, 1);   // loads row 173 (last input row)
    ROW_STEP(4, 1, 0);
    ROW_STEP(5, 1, 0);

    // ---- block reduction -> partial; last block finishes ----
    float acc = acc0 + acc1;
    #pragma unroll
    for (int o = 16; o > 0; o >>= 1)
        acc += __shfl_xor_sync(0xFFFFFFFFu, acc, o);
    if (lane == 0) smn[wid] = acc;
    __syncthreads();
    if (tid == 0){
        float s = smn[0];
        #pragma unroll
        for (int w = 1; w < 8; ++w) s += smn[w];
        g_part[bx] = s;
        __threadfence();
        s_tick = atomicAdd(&g_done, 1u);
    }
    __syncthreads();

    if (s_tick == (unsigned)(nblk - 1)){
        double s = 0.0;
        for (int i = tid; i < nblk; i += 256) s += (double)g_part[i];
        #pragma unroll
        for (int o = 16; o > 0; o >>= 1)
            s += __shfl_xor_sync(0xFFFFFFFFu, s, o);
        if (lane == 0) sd[wid] = s;
        __syncthreads();
        if (tid == 0){
            double t = 0.0;
            #pragma unroll
            for (int w = 0; w < 8; ++w) t += sd[w];
            out[0] = (float)((1.0 - t * inv_n) * 0.5);
            g_done = 0u;   // reset for next graph replay
        }
    }
}

// ---------------- launch --------------------------------------------------------
extern "C" void kernel_launch(void* const* d_in, const int* in_sizes, int n_in,
                              void* d_out, int out_size){
    const float* X = (const float*)d_in[0];  // y_pred
    const float* Y = (const float*)d_in[1];  // y_true

    const int nelem = in_sizes[0];
    const int nimg  = nelem / (IMG_W * IMG_W);
    const int nblk  = NSTR * nimg;
    const double n_out = (double)nimg * (double)OUT_W * (double)OUT_W;

    k_minmax<<<NB_MM, 256>>>((const float4*)X, nelem / 4);
    k_ssim<<<nblk, 256>>>(X, Y, (float*)d_out, nblk, 1.0 / n_out);
}

// round 10
// speedup vs baseline: 1.1799x; 1.0190x over previous
#include <cuda_runtime.h>
#include <cstdint>

typedef unsigned long long ull;

#define IMG_W 512
#define OUT_W 507
#define NSTR  3       // strips per image
#define STRIP 169     // output rows per strip (3*169 = 507 exact)
#define NROWS 174     // input rows per strip (STRIP + 5), divisible by 6
#define NB_MM 1184
#define SEGF  72      // floats per warp row segment (64 + 6 halo + 2 pad)
#define NSLOT 6       // smem ring slots per warp (lead-4 pipeline)

// ---------------- device-global scratch (no allocs) --------------------------
__device__ float    g_mn[NB_MM], g_mx[NB_MM];
__device__ float    g_part[512];
__device__ unsigned g_done;          // zero-init; last block resets each run

// ---------------- packed f32x2 helpers (sm_103a) ------------------------------
static __device__ __forceinline__ ull pk2(float a, float b){
    ull r; asm("mov.b64 %0, {%1, %2};" : "=l"(r) : "f"(a), "f"(b)); return r;
}
static __device__ __forceinline__ ull mul2(ull a, ull b){
    ull r; asm("mul.rn.f32x2 %0, %1, %2;" : "=l"(r) : "l"(a), "l"(b)); return r;
}
static __device__ __forceinline__ ull add2(ull a, ull b){
    ull r; asm("add.rn.f32x2 %0, %1, %2;" : "=l"(r) : "l"(a), "l"(b)); return r;
}
static __device__ __forceinline__ ull fma2(ull a, ull b, ull c){
    ull r; asm("fma.rn.f32x2 %0, %1, %2, %3;" : "=l"(r) : "l"(a), "l"(b), "l"(c)); return r;
}
static __device__ __forceinline__ float lo2(ull a){ return __uint_as_float((unsigned)a); }
static __device__ __forceinline__ float hi2(ull a){ return __uint_as_float((unsigned)(a >> 32)); }

static __device__ __forceinline__ void cpa16(unsigned dst, const void* src){
    asm volatile("cp.async.ca.shared.global [%0], [%1], 16;" :: "r"(dst), "l"(src) : "memory");
}
static __device__ __forceinline__ void cpa_commit(){
    asm volatile("cp.async.commit_group;" ::: "memory");
}
static __device__ __forceinline__ void cpa_wait4(){
    asm volatile("cp.async.wait_group 4;" ::: "memory");
}

// ---------------- gaussian weights (w_size=6, sigma=1.5, normalized) ---------
#define GW0 0.03802585f
#define GW1 0.11551231f
#define GW2 0.22498725f
#define GW3 0.28097506f

// ---------------- min/max partials kernel -------------------------------------
__global__ void k_minmax(const float4* __restrict__ x, int n4){
    float mn = 3.4028235e38f, mx = -3.4028235e38f;
    int stride = gridDim.x * blockDim.x;
    for (int i = blockIdx.x * blockDim.x + threadIdx.x; i < n4; i += stride){
        float4 v = x[i];
        mn = fminf(mn, fminf(fminf(v.x, v.y), fminf(v.z, v.w)));
        mx = fmaxf(mx, fmaxf(fmaxf(v.x, v.y), fmaxf(v.z, v.w)));
    }
    #pragma unroll
    for (int o = 16; o > 0; o >>= 1){
        mn = fminf(mn, __shfl_xor_sync(0xFFFFFFFFu, mn, o));
        mx = fmaxf(mx, __shfl_xor_sync(0xFFFFFFFFu, mx, o));
    }
    __shared__ float smn[8], smx[8];
    int wid = threadIdx.x >> 5, lane = threadIdx.x & 31;
    if (lane == 0){ smn[wid] = mn; smx[wid] = mx; }
    __syncthreads();
    if (threadIdx.x == 0){
        mn = smn[0]; mx = smx[0];
        #pragma unroll
        for (int w = 1; w < 8; ++w){ mn = fminf(mn, smn[w]); mx = fmaxf(mx, smx[w]); }
        g_mn[blockIdx.x] = mn;
        g_mx[blockIdx.x] = mx;
    }
}

// 6-tap packed MAC: taps [GW0,GW1,GW2,GW3,GW2,GW1]
#define HMAC(d, v0, v1, v2, v3, v4, v5) \
    d = mul2((v0), W0); d = fma2((v1), W1, d); d = fma2((v2), W2, d); \
    d = fma2((v3), W3, d); d = fma2((v4), W2, d); d = fma2((v5), W1, d)

// One row-step. P literal 0..5. DOLOAD compile-time 0/1.
// Loads row i+4 into smem slot (P+4)%6 via cp.async; consumes row i from slot P%6.
// xsrc/ysrc point at row (group_start + 4).
#define ROW_STEP(P, DOOUT, DOLOAD) do { \
    if (DOLOAD && lane18){ \
        cpa16(sxw + (((P)+4)%NSLOT)*(SEGF*4) + lane16, xsrc + (P)*2048); \
        cpa16(syw + (((P)+4)%NSLOT)*(SEGF*4) + lane16, ysrc + (P)*2048); \
    } \
    cpa_commit(); \
    cpa_wait4(); \
    __syncwarp(); \
    { \
        const float* bx_ = &swx[(P)%NSLOT][lane2]; \
        const float* by_ = &swy[(P)%NSLOT][lane2]; \
        float2 X0_ = *(const float2*)(bx_    ); \
        float2 X1_ = *(const float2*)(bx_ + 2); \
        float2 X2_ = *(const float2*)(bx_ + 4); \
        float2 X3_ = *(const float2*)(bx_ + 6); \
        float2 Y0_ = *(const float2*)(by_    ); \
        float2 Y1_ = *(const float2*)(by_ + 2); \
        float2 Y2_ = *(const float2*)(by_ + 4); \
        float2 Y3_ = *(const float2*)(by_ + 6); \
        ull xp0_ = pk2(X0_.x, X0_.y), xp1_ = pk2(X1_.x, X1_.y); \
        ull xp2_ = pk2(X2_.x, X2_.y), xp3_ = pk2(X3_.x, X3_.y); \
        ull yp0_ = pk2(Y0_.x, Y0_.y), yp1_ = pk2(Y1_.x, Y1_.y); \
        ull yp2_ = pk2(Y2_.x, Y2_.y), yp3_ = pk2(Y3_.x, Y3_.y); \
        ull pp0_ = fma2(yp0_, yp0_, mul2(xp0_, xp0_)); \
        ull pp1_ = fma2(yp1_, yp1_, mul2(xp1_, xp1_)); \
        ull pp2_ = fma2(yp2_, yp2_, mul2(xp2_, xp2_)); \
        ull pp3_ = fma2(yp3_, yp3_, mul2(xp3_, xp3_)); \
        ull qq0_ = mul2(xp0_, yp0_), qq1_ = mul2(xp1_, yp1_); \
        ull qq2_ = mul2(xp2_, yp2_), qq3_ = mul2(xp3_, yp3_); \
        { ull d_; HMAC(d_, xp0_, pk2(X0_.y, X1_.x), xp1_, pk2(X1_.y, X2_.x), xp2_, pk2(X2_.y, X3_.x)); ring[(P)][0] = d_; } \
        { ull d_; HMAC(d_, yp0_, pk2(Y0_.y, Y1_.x), yp1_, pk2(Y1_.y, Y2_.x), yp2_, pk2(Y2_.y, Y3_.x)); ring[(P)][1] = d_; } \
        { ull d_; HMAC(d_, pp0_, pk2(hi2(pp0_), lo2(pp1_)), pp1_, pk2(hi2(pp1_), lo2(pp2_)), pp2_, pk2(hi2(pp2_), lo2(pp3_))); ring[(P)][2] = d_; } \
        { ull d_; HMAC(d_, qq0_, pk2(hi2(qq0_), lo2(qq1_)), qq1_, pk2(hi2(qq1_), lo2(qq2_)), qq2_, pk2(hi2(qq2_), lo2(qq3_))); ring[(P)][3] = d_; } \
    } \
    if (DOOUT){ \
        ull v0_, v1_, v2_, v3_; \
        HMAC(v0_, ring[((P)+1)%6][0], ring[((P)+2)%6][0], ring[((P)+3)%6][0], ring[((P)+4)%6][0], ring[((P)+5)%6][0], ring[(P)][0]); \
        HMAC(v1_, ring[((P)+1)%6][1], ring[((P)+2)%6][1], ring[((P)+3)%6][1], ring[((P)+4)%6][1], ring[((P)+5)%6][1], ring[(P)][1]); \
        HMAC(v2_, ring[((P)+1)%6][2], ring[((P)+2)%6][2], ring[((P)+3)%6][2], ring[((P)+4)%6][2], ring[((P)+5)%6][2], ring[(P)][2]); \
        HMAC(v3_, ring[((P)+1)%6][3], ring[((P)+2)%6][3], ring[((P)+3)%6][3], ring[((P)+4)%6][3], ring[((P)+5)%6][3], ring[(P)][3]); \
        ull mu12_ = mul2(v0_, v1_); \
        ull msum_ = fma2(v1_, v1_, mul2(v0_, v0_)); \
        ull t1_ = fma2(mu12_, NTWO, fma2(v3_, TWO, C2p)); \
        ull t2_ = fma2(msum_, NONE, add2(v2_, C2p)); \
        ull num_ = mul2(fma2(mu12_, TWO, C1p), t1_); \
        ull den_ = mul2(add2(msum_, C1p), t2_); \
        if (lo_ok) acc0 += __fdividef(lo2(num_), lo2(den_)); \
        if (hi_ok) acc1 += __fdividef(hi2(num_), hi2(den_)); \
    } \
} while(0)

__global__ void __launch_bounds__(256, 2)
k_ssim(const float* __restrict__ X, const float* __restrict__ Y,
       float* __restrict__ out, int nblk, double inv_n){
    // warp-private row rings: [warp][slot][72 floats] per tensor
    __shared__ float s_x[8][NSLOT][SEGF];
    __shared__ float s_y[8][NSLOT][SEGF];
    __shared__ float    smn[8], smx[8], sC[2];
    __shared__ double   sd[8];
    __shared__ unsigned s_tick;

    const int tid   = threadIdx.x;
    const int wid   = tid >> 5;
    const int lane  = tid & 31;
    const int wc0   = wid * 64;            // warp's first output column
    const int c0    = wc0 + lane * 2;      // this thread's first output column
    const int lane2 = lane * 2;            // float offset within segment
    const int bx    = blockIdx.x;
    const int strip = bx % NSTR;
    const int img   = bx / NSTR;
    const int base  = strip * STRIP;
    const float* xi = X + (size_t)img * (IMG_W * IMG_W);
    const float* yi = Y + (size_t)img * (IMG_W * IMG_W);
    const bool lo_ok = (c0     < OUT_W);
    const bool hi_ok = (c0 + 1 < OUT_W);
    const bool lane18 = (lane < 18);

    // cp.async source column for this lane (16B granule), clamped to row end
    const int scol   = min(wc0 + lane * 4, 508);
    const int lane16 = lane * 16;          // byte offset within segment

    // running source byte pointers -> row (base+4) [group_start + 4]
    const char* xsrc = (const char*)(xi + (size_t)(base + 4) * IMG_W + scol);
    const char* ysrc = (const char*)(yi + (size_t)(base + 4) * IMG_W + scol);

    // smem u32 addresses of this warp's ring bases
    const unsigned sxw = (unsigned)__cvta_generic_to_shared(&s_x[wid][0][0]);
    const unsigned syw = (unsigned)__cvta_generic_to_shared(&s_y[wid][0][0]);
    const float (*swx)[SEGF] = s_x[wid];
    const float (*swy)[SEGF] = s_y[wid];

    // ---- reduce min/max partials -> C1, C2 ----
    {
        float mn = 3.4028235e38f, mx = -3.4028235e38f;
        for (int i = tid; i < NB_MM; i += 256){
            mn = fminf(mn, g_mn[i]);
            mx = fmaxf(mx, g_mx[i]);
        }
        #pragma unroll
        for (int o = 16; o > 0; o >>= 1){
            mn = fminf(mn, __shfl_xor_sync(0xFFFFFFFFu, mn, o));
            mx = fmaxf(mx, __shfl_xor_sync(0xFFFFFFFFu, mx, o));
        }
        if (lane == 0){ smn[wid] = mn; smx[wid] = mx; }
    }

    // prologue: rows base+0..base+3 -> slots 0..3 (one commit group per row)
    #pragma unroll
    for (int r = 0; r < 4; ++r){
        if (lane18){
            cpa16(sxw + r*(SEGF*4) + lane16, xsrc + (r - 4)*2048);
            cpa16(syw + r*(SEGF*4) + lane16, ysrc + (r - 4)*2048);
        }
        cpa_commit();
    }

    __syncthreads();
    if (tid == 0){
        float mn = smn[0], mx = smx[0];
        #pragma unroll
        for (int w = 1; w < 8; ++w){ mn = fminf(mn, smn[w]); mx = fmaxf(mx, smx[w]); }
        float Ldyn = (mx > 128.0f ? 255.0f : 1.0f) - (mn < -0.5f ? -1.0f : 0.0f);
        sC[0] = (0.01f * Ldyn) * (0.01f * Ldyn);
        sC[1] = (0.03f * Ldyn) * (0.03f * Ldyn);
    }
    __syncthreads();

    const float C1 = sC[0], C2 = sC[1];
    const ull W0  = pk2(GW0, GW0), W1 = pk2(GW1, GW1);
    const ull W2  = pk2(GW2, GW2), W3 = pk2(GW3, GW3);
    const ull C1p = pk2(C1, C1),   C2p = pk2(C2, C2);
    const ull TWO = pk2(2.0f, 2.0f), NTWO = pk2(-2.0f, -2.0f), NONE = pk2(-1.0f, -1.0f);

    ull ring[6][4];
    float acc0 = 0.0f, acc1 = 0.0f;

    // ---- group 0 (rows 0..5): warm-up, first output at row 5; loads rows 4..9 ----
    ROW_STEP(0, 0, 1);
    ROW_STEP(1, 0, 1);
    ROW_STEP(2, 0, 1);
    ROW_STEP(3, 0, 1);
    ROW_STEP(4, 0, 1);
    ROW_STEP(5, 1, 1);
    xsrc += 6*2048; ysrc += 6*2048;

    // ---- middle groups (rows 6..167): fully clean; loads rows 10..171 ----
    #pragma unroll 1
    for (int g = 0; g < 27; ++g){
        ROW_STEP(0, 1, 1);
        ROW_STEP(1, 1, 1);
        ROW_STEP(2, 1, 1);
        ROW_STEP(3, 1, 1);
        ROW_STEP(4, 1, 1);
        ROW_STEP(5, 1, 1);
        xsrc += 6*2048; ysrc += 6*2048;
    }

    // ---- tail group (rows 168..173): loads rows 172,173 then stop ----
    ROW_STEP(0, 1, 1);   // loads row 172
    ROW_STEP(1, 1, 1);   // loads row 173 (last input row)
    ROW_STEP(2, 1, 0);
    ROW_STEP(3, 1, 0);
    ROW_STEP(4, 1, 0);
    ROW_STEP(5, 1, 0);

    // ---- block reduction -> partial; last block finishes ----
    float acc = acc0 + acc1;
    #pragma unroll
    for (int o = 16; o > 0; o >>= 1)
        acc += __shfl_xor_sync(0xFFFFFFFFu, acc, o);
    if (lane == 0) smn[wid] = acc;
    __syncthreads();
    if (tid == 0){
        float s = smn[0];
        #pragma unroll
        for (int w = 1; w < 8; ++w) s += smn[w];
        g_part[bx] = s;
        __threadfence();
        s_tick = atomicAdd(&g_done, 1u);
    }
    __syncthreads();

    if (s_tick == (unsigned)(nblk - 1)){
        double s = 0.0;
        for (int i = tid; i < nblk; i += 256) s += (double)g_part[i];
        #pragma unroll
        for (int o = 16; o > 0; o >>= 1)
            s += __shfl_xor_sync(0xFFFFFFFFu, s, o);
        if (lane == 0) sd[wid] = s;
        __syncthreads();
        if (tid == 0){
            double t = 0.0;
            #pragma unroll
            for (int w = 0; w < 8; ++w) t += sd[w];
            out[0] = (float)((1.0 - t * inv_n) * 0.5);
            g_done = 0u;   // reset for next graph replay
        }
    }
}

// ---------------- launch --------------------------------------------------------
extern "C" void kernel_launch(void* const* d_in, const int* in_sizes, int n_in,
                              void* d_out, int out_size){
    const float* X = (const float*)d_in[0];  // y_pred
    const float* Y = (const float*)d_in[1];  // y_true

    const int nelem = in_sizes[0];
    const int nimg  = nelem / (IMG_W * IMG_W);
    const int nblk  = NSTR * nimg;
    const double n_out = (double)nimg * (double)OUT_W * (double)OUT_W;

    k_minmax<<<NB_MM, 256>>>((const float4*)X, nelem / 4);
    k_ssim<<<nblk, 256>>>(X, Y, (float*)d_out, nblk, 1.0 / n_out);
}

// round 11
// speedup vs baseline: 1.1955x; 1.0132x over previous
#include <cuda_runtime.h>
#include <cstdint>

typedef unsigned long long ull;

#define IMG_W 512
#define OUT_W 507
#define NSTR  3       // strips per image
#define STRIP 169     // output rows per strip (3*169 = 507 exact)
#define NROWS 174     // input rows per strip (STRIP + 5), divisible by 6
#define NB_MM 1184
#define SEGF  72      // floats per warp row segment (64 + 6 halo + 2 pad)
#define NSLOT 6       // smem ring slots per warp

// ---------------- device-global scratch (no allocs) --------------------------
__device__ float    g_mn[NB_MM], g_mx[NB_MM];
__device__ float    g_part[512];
__device__ unsigned g_done;          // zero-init; last block resets each run

// ---------------- packed f32x2 helpers (sm_103a) ------------------------------
static __device__ __forceinline__ ull pk2(float a, float b){
    ull r; asm("mov.b64 %0, {%1, %2};" : "=l"(r) : "f"(a), "f"(b)); return r;
}
static __device__ __forceinline__ ull mul2(ull a, ull b){
    ull r; asm("mul.rn.f32x2 %0, %1, %2;" : "=l"(r) : "l"(a), "l"(b)); return r;
}
static __device__ __forceinline__ ull add2(ull a, ull b){
    ull r; asm("add.rn.f32x2 %0, %1, %2;" : "=l"(r) : "l"(a), "l"(b)); return r;
}
static __device__ __forceinline__ ull fma2(ull a, ull b, ull c){
    ull r; asm("fma.rn.f32x2 %0, %1, %2, %3;" : "=l"(r) : "l"(a), "l"(b), "l"(c)); return r;
}
static __device__ __forceinline__ float lo2(ull a){ return __uint_as_float((unsigned)a); }
static __device__ __forceinline__ float hi2(ull a){ return __uint_as_float((unsigned)(a >> 32)); }

static __device__ __forceinline__ void cpa16(unsigned dst, const void* src){
    asm volatile("cp.async.ca.shared.global [%0], [%1], 16;" :: "r"(dst), "l"(src) : "memory");
}
static __device__ __forceinline__ void cpa_commit(){
    asm volatile("cp.async.commit_group;" ::: "memory");
}
static __device__ __forceinline__ void cpa_wait2(){
    asm volatile("cp.async.wait_group 2;" ::: "memory");
}

// ---------------- gaussian weights (w_size=6, sigma=1.5, normalized) ---------
#define GW0 0.03802585f
#define GW1 0.11551231f
#define GW2 0.22498725f
#define GW3 0.28097506f

// ---------------- min/max partials kernel -------------------------------------
__global__ void k_minmax(const float4* __restrict__ x, int n4){
    float mn = 3.4028235e38f, mx = -3.4028235e38f;
    int stride = gridDim.x * blockDim.x;
    for (int i = blockIdx.x * blockDim.x + threadIdx.x; i < n4; i += stride){
        float4 v = x[i];
        mn = fminf(mn, fminf(fminf(v.x, v.y), fminf(v.z, v.w)));
        mx = fmaxf(mx, fmaxf(fmaxf(v.x, v.y), fmaxf(v.z, v.w)));
    }
    #pragma unroll
    for (int o = 16; o > 0; o >>= 1){
        mn = fminf(mn, __shfl_xor_sync(0xFFFFFFFFu, mn, o));
        mx = fmaxf(mx, __shfl_xor_sync(0xFFFFFFFFu, mx, o));
    }
    __shared__ float smn[8], smx[8];
    int wid = threadIdx.x >> 5, lane = threadIdx.x & 31;
    if (lane == 0){ smn[wid] = mn; smx[wid] = mx; }
    __syncthreads();
    if (threadIdx.x == 0){
        mn = smn[0]; mx = smx[0];
        #pragma unroll
        for (int w = 1; w < 8; ++w){ mn = fminf(mn, smn[w]); mx = fmaxf(mx, smx[w]); }
        g_mn[blockIdx.x] = mn;
        g_mx[blockIdx.x] = mx;
    }
}

// 6-tap packed MAC: taps [GW0,GW1,GW2,GW3,GW2,GW1]
#define HMAC(d, v0, v1, v2, v3, v4, v5) \
    d = mul2((v0), W0); d = fma2((v1), W1, d); d = fma2((v2), W2, d); \
    d = fma2((v3), W3, d); d = fma2((v4), W2, d); d = fma2((v5), W1, d)

// Compute one row from smem slot P%6; horizontal conv into ring[P]; optional output.
#define ROW_COMPUTE(P, DOOUT) do { \
    { \
        const float* bx_ = &swx[(P)%NSLOT][lane2]; \
        const float* by_ = &swy[(P)%NSLOT][lane2]; \
        float2 X0_ = *(const float2*)(bx_    ); \
        float2 X1_ = *(const float2*)(bx_ + 2); \
        float2 X2_ = *(const float2*)(bx_ + 4); \
        float2 X3_ = *(const float2*)(bx_ + 6); \
        float2 Y0_ = *(const float2*)(by_    ); \
        float2 Y1_ = *(const float2*)(by_ + 2); \
        float2 Y2_ = *(const float2*)(by_ + 4); \
        float2 Y3_ = *(const float2*)(by_ + 6); \
        ull xp0_ = pk2(X0_.x, X0_.y), xp1_ = pk2(X1_.x, X1_.y); \
        ull xp2_ = pk2(X2_.x, X2_.y), xp3_ = pk2(X3_.x, X3_.y); \
        ull yp0_ = pk2(Y0_.x, Y0_.y), yp1_ = pk2(Y1_.x, Y1_.y); \
        ull yp2_ = pk2(Y2_.x, Y2_.y), yp3_ = pk2(Y3_.x, Y3_.y); \
        ull pp0_ = fma2(yp0_, yp0_, mul2(xp0_, xp0_)); \
        ull pp1_ = fma2(yp1_, yp1_, mul2(xp1_, xp1_)); \
        ull pp2_ = fma2(yp2_, yp2_, mul2(xp2_, xp2_)); \
        ull pp3_ = fma2(yp3_, yp3_, mul2(xp3_, xp3_)); \
        ull qq0_ = mul2(xp0_, yp0_), qq1_ = mul2(xp1_, yp1_); \
        ull qq2_ = mul2(xp2_, yp2_), qq3_ = mul2(xp3_, yp3_); \
        { ull d_; HMAC(d_, xp0_, pk2(X0_.y, X1_.x), xp1_, pk2(X1_.y, X2_.x), xp2_, pk2(X2_.y, X3_.x)); ring[(P)][0] = d_; } \
        { ull d_; HMAC(d_, yp0_, pk2(Y0_.y, Y1_.x), yp1_, pk2(Y1_.y, Y2_.x), yp2_, pk2(Y2_.y, Y3_.x)); ring[(P)][1] = d_; } \
        { ull d_; HMAC(d_, pp0_, pk2(hi2(pp0_), lo2(pp1_)), pp1_, pk2(hi2(pp1_), lo2(pp2_)), pp2_, pk2(hi2(pp2_), lo2(pp3_))); ring[(P)][2] = d_; } \
        { ull d_; HMAC(d_, qq0_, pk2(hi2(qq0_), lo2(qq1_)), qq1_, pk2(hi2(qq1_), lo2(qq2_)), qq2_, pk2(hi2(qq2_), lo2(qq3_))); ring[(P)][3] = d_; } \
    } \
    if (DOOUT){ \
        ull v0_, v1_, v2_, v3_; \
        HMAC(v0_, ring[((P)+1)%6][0], ring[((P)+2)%6][0], ring[((P)+3)%6][0], ring[((P)+4)%6][0], ring[((P)+5)%6][0], ring[(P)][0]); \
        HMAC(v1_, ring[((P)+1)%6][1], ring[((P)+2)%6][1], ring[((P)+3)%6][1], ring[((P)+4)%6][1], ring[((P)+5)%6][1], ring[(P)][1]); \
        HMAC(v2_, ring[((P)+1)%6][2], ring[((P)+2)%6][2], ring[((P)+3)%6][2], ring[((P)+4)%6][2], ring[((P)+5)%6][2], ring[(P)][2]); \
        HMAC(v3_, ring[((P)+1)%6][3], ring[((P)+2)%6][3], ring[((P)+3)%6][3], ring[((P)+4)%6][3], ring[((P)+5)%6][3], ring[(P)][3]); \
        ull mu12_ = mul2(v0_, v1_); \
        ull msum_ = fma2(v1_, v1_, mul2(v0_, v0_)); \
        ull t1_ = fma2(mu12_, NTWO, fma2(v3_, TWO, C2p)); \
        ull t2_ = fma2(msum_, NONE, add2(v2_, C2p)); \
        ull num_ = mul2(fma2(mu12_, TWO, C1p), t1_); \
        ull den_ = mul2(add2(msum_, C1p), t2_); \
        if (lo_ok) acc0 += __fdividef(lo2(num_), lo2(den_)); \
        if (hi_ok) acc1 += __fdividef(hi2(num_), hi2(den_)); \
    } \
} while(0)

// Pair-step: P literal in {0,2,4}. Commits rows P+4,P+5 (one group), one wait +
// one syncwarp, then computes rows P and P+1 with no barrier between them.
#define PAIR_STEP(P, DOOUT0, DOOUT1, DOLOAD) do { \
    if (DOLOAD && lane18){ \
        cpa16(sxw + (((P)+4)%NSLOT)*(SEGF*4) + lane16, xsrc + (P)*2048); \
        cpa16(syw + (((P)+4)%NSLOT)*(SEGF*4) + lane16, ysrc + (P)*2048); \
        cpa16(sxw + (((P)+5)%NSLOT)*(SEGF*4) + lane16, xsrc + ((P)+1)*2048); \
        cpa16(syw + (((P)+5)%NSLOT)*(SEGF*4) + lane16, ysrc + ((P)+1)*2048); \
    } \
    cpa_commit(); \
    cpa_wait2(); \
    __syncwarp(); \
    ROW_COMPUTE(P, DOOUT0); \
    ROW_COMPUTE((P)+1, DOOUT1); \
} while(0)

__global__ void __launch_bounds__(256, 2)
k_ssim(const float* __restrict__ X, const float* __restrict__ Y,
       float* __restrict__ out, int nblk, double inv_n){
    // warp-private row rings: [warp][slot][72 floats] per tensor
    __shared__ float s_x[8][NSLOT][SEGF];
    __shared__ float s_y[8][NSLOT][SEGF];
    __shared__ float    smn[8], smx[8], sC[2];
    __shared__ double   sd[8];
    __shared__ unsigned s_tick;

    const int tid   = threadIdx.x;
    const int wid   = tid >> 5;
    const int lane  = tid & 31;
    const int wc0   = wid * 64;            // warp's first output column
    const int c0    = wc0 + lane * 2;      // this thread's first output column
    const int lane2 = lane * 2;            // float offset within segment
    const int bx    = blockIdx.x;
    const int strip = bx % NSTR;
    const int img   = bx / NSTR;
    const int base  = strip * STRIP;
    const float* xi = X + (size_t)img * (IMG_W * IMG_W);
    const float* yi = Y + (size_t)img * (IMG_W * IMG_W);
    const bool lo_ok = (c0     < OUT_W);
    const bool hi_ok = (c0 + 1 < OUT_W);
    const bool lane18 = (lane < 18);

    // cp.async source column for this lane (16B granule), clamped to row end
    const int scol   = min(wc0 + lane * 4, 508);
    const int lane16 = lane * 16;          // byte offset within segment

    // running source byte pointers -> row (group_start + 4)
    const char* xsrc = (const char*)(xi + (size_t)(base + 4) * IMG_W + scol);
    const char* ysrc = (const char*)(yi + (size_t)(base + 4) * IMG_W + scol);

    // smem u32 addresses of this warp's ring bases
    const unsigned sxw = (unsigned)__cvta_generic_to_shared(&s_x[wid][0][0]);
    const unsigned syw = (unsigned)__cvta_generic_to_shared(&s_y[wid][0][0]);
    const float (*swx)[SEGF] = s_x[wid];
    const float (*swy)[SEGF] = s_y[wid];

    // ---- reduce min/max partials -> C1, C2 ----
    {
        float mn = 3.4028235e38f, mx = -3.4028235e38f;
        for (int i = tid; i < NB_MM; i += 256){
            mn = fminf(mn, g_mn[i]);
            mx = fmaxf(mx, g_mx[i]);
        }
        #pragma unroll
        for (int o = 16; o > 0; o >>= 1){
            mn = fminf(mn, __shfl_xor_sync(0xFFFFFFFFu, mn, o));
            mx = fmaxf(mx, __shfl_xor_sync(0xFFFFFFFFu, mx, o));
        }
        if (lane == 0){ smn[wid] = mn; smx[wid] = mx; }
    }

    // prologue: rows base+0,base+1 -> group A (slots 0,1); rows base+2,base+3 -> group B (slots 2,3)
    if (lane18){
        cpa16(sxw + 0*(SEGF*4) + lane16, xsrc - 4*2048);
        cpa16(syw + 0*(SEGF*4) + lane16, ysrc - 4*2048);
        cpa16(sxw + 1*(SEGF*4) + lane16, xsrc - 3*2048);
        cpa16(syw + 1*(SEGF*4) + lane16, ysrc - 3*2048);
    }
    cpa_commit();
    if (lane18){
        cpa16(sxw + 2*(SEGF*4) + lane16, xsrc - 2*2048);
        cpa16(syw + 2*(SEGF*4) + lane16, ysrc - 2*2048);
        cpa16(sxw + 3*(SEGF*4) + lane16, xsrc - 1*2048);
        cpa16(syw + 3*(SEGF*4) + lane16, ysrc - 1*2048);
    }
    cpa_commit();

    __syncthreads();
    if (tid == 0){
        float mn = smn[0], mx = smx[0];
        #pragma unroll
        for (int w = 1; w < 8; ++w){ mn = fminf(mn, smn[w]); mx = fmaxf(mx, smx[w]); }
        float Ldyn = (mx > 128.0f ? 255.0f : 1.0f) - (mn < -0.5f ? -1.0f : 0.0f);
        sC[0] = (0.01f * Ldyn) * (0.01f * Ldyn);
        sC[1] = (0.03f * Ldyn) * (0.03f * Ldyn);
    }
    __syncthreads();

    const float C1 = sC[0], C2 = sC[1];
    const ull W0  = pk2(GW0, GW0), W1 = pk2(GW1, GW1);
    const ull W2  = pk2(GW2, GW2), W3 = pk2(GW3, GW3);
    const ull C1p = pk2(C1, C1),   C2p = pk2(C2, C2);
    const ull TWO = pk2(2.0f, 2.0f), NTWO = pk2(-2.0f, -2.0f), NONE = pk2(-1.0f, -1.0f);

    ull ring[6][4];
    float acc0 = 0.0f, acc1 = 0.0f;

    // ---- group 0 (rows 0..5): warm-up, first output at row 5; loads rows 4..9 ----
    PAIR_STEP(0, 0, 0, 1);
    PAIR_STEP(2, 0, 0, 1);
    PAIR_STEP(4, 0, 1, 1);
    xsrc += 6*2048; ysrc += 6*2048;

    // ---- middle groups (rows 6..167): fully clean; loads rows 10..171 ----
    #pragma unroll 1
    for (int g = 0; g < 27; ++g){
        PAIR_STEP(0, 1, 1, 1);
        PAIR_STEP(2, 1, 1, 1);
        PAIR_STEP(4, 1, 1, 1);
        xsrc += 6*2048; ysrc += 6*2048;
    }

    // ---- tail group (rows 168..173): loads rows 172,173 then stop ----
    PAIR_STEP(0, 1, 1, 1);   // loads rows 172,173
    PAIR_STEP(2, 1, 1, 0);
    PAIR_STEP(4, 1, 1, 0);

    // ---- block reduction -> partial; last block finishes ----
    float acc = acc0 + acc1;
    #pragma unroll
    for (int o = 16; o > 0; o >>= 1)
        acc += __shfl_xor_sync(0xFFFFFFFFu, acc, o);
    if (lane == 0) smn[wid] = acc;
    __syncthreads();
    if (tid == 0){
        float s = smn[0];
        #pragma unroll
        for (int w = 1; w < 8; ++w) s += smn[w];
        g_part[bx] = s;
        __threadfence();
        s_tick = atomicAdd(&g_done, 1u);
    }
    __syncthreads();

    if (s_tick == (unsigned)(nblk - 1)){
        double s = 0.0;
        for (int i = tid; i < nblk; i += 256) s += (double)g_part[i];
        #pragma unroll
        for (int o = 16; o > 0; o >>= 1)
            s += __shfl_xor_sync(0xFFFFFFFFu, s, o);
        if (lane == 0) sd[wid] = s;
        __syncthreads();
        if (tid == 0){
            double t = 0.0;
            #pragma unroll
            for (int w = 0; w < 8; ++w) t += sd[w];
            out[0] = (float)((1.0 - t * inv_n) * 0.5);
            g_done = 0u;   // reset for next graph replay
        }
    }
}

// ---------------- launch --------------------------------------------------------
extern "C" void kernel_launch(void* const* d_in, const int* in_sizes, int n_in,
                              void* d_out, int out_size){
    const float* X = (const float*)d_in[0];  // y_pred
    const float* Y = (const float*)d_in[1];  // y_true

    const int nelem = in_sizes[0];
    const int nimg  = nelem / (IMG_W * IMG_W);
    const int nblk  = NSTR * nimg;
    const double n_out = (double)nimg * (double)OUT_W * (double)OUT_W;

    k_minmax<<<NB_MM, 256>>>((const float4*)X, nelem / 4);
    k_ssim<<<nblk, 256>>>(X, Y, (float*)d_out, nblk, 1.0 / n_out);
}